// round 1
// baseline (speedup 1.0000x reference)
#include <cuda_runtime.h>
#include <math.h>
#include <stdint.h>

// ---------------- problem constants ----------------
#define BB      16
#define PP      2048
#define DD      512
#define HH      8
#define CC      64
#define HD_     64
#define MM      (BB * PP)        // 32768
#define FFNIN   1024
#define FFNHID  4096

// ---------------- scratch (device globals; allocation-free) ----------------
__device__ float g_q[MM * DD];                    //  64 MB  q = input@Wv+bv
__device__ float g_aff[BB * HH * CC * PP];        //  64 MB  aff -> (in-place) a_core_to_patch
__device__ float g_p2c[BB * HH * CC * PP];        //  64 MB  a_patch_to_core
__device__ float g_vcore[BB * HH * CC * HD_];     //   2 MB
__device__ float g_ffn[MM * FFNIN];               // 128 MB  [input-v_out, v_out]
__device__ float g_hid[(size_t)MM * FFNHID];      // 512 MB
__device__ float g_outp[MM * DD];                 //  64 MB  pre-LN

// ---------------- helpers ----------------
__device__ __forceinline__ float gelu_exact(float x) {
    return 0.5f * x * (1.0f + erff(x * 0.7071067811865476f));
}

__device__ __forceinline__ float blockReduceMax(float v) {
    __shared__ float sm[8];
    #pragma unroll
    for (int o = 16; o > 0; o >>= 1) v = fmaxf(v, __shfl_xor_sync(0xffffffffu, v, o));
    int wid = threadIdx.x >> 5, nw = blockDim.x >> 5;
    if ((threadIdx.x & 31) == 0) sm[wid] = v;
    __syncthreads();
    float r = -1e30f;
    for (int i = 0; i < nw; ++i) r = fmaxf(r, sm[i]);
    __syncthreads();
    return r;
}

__device__ __forceinline__ float blockReduceSum(float v) {
    __shared__ float sm[8];
    #pragma unroll
    for (int o = 16; o > 0; o >>= 1) v += __shfl_xor_sync(0xffffffffu, v, o);
    int wid = threadIdx.x >> 5, nw = blockDim.x >> 5;
    if ((threadIdx.x & 31) == 0) sm[wid] = v;
    __syncthreads();
    float r = 0.0f;
    for (int i = 0; i < nw; ++i) r += sm[i];
    __syncthreads();
    return r;
}

__device__ __forceinline__ void blockReduceSum2(float& a, float& b) {
    __shared__ float sa[8], sb[8];
    #pragma unroll
    for (int o = 16; o > 0; o >>= 1) {
        a += __shfl_xor_sync(0xffffffffu, a, o);
        b += __shfl_xor_sync(0xffffffffu, b, o);
    }
    int wid = threadIdx.x >> 5, nw = blockDim.x >> 5;
    if ((threadIdx.x & 31) == 0) { sa[wid] = a; sb[wid] = b; }
    __syncthreads();
    float ra = 0.0f, rb = 0.0f;
    for (int i = 0; i < nw; ++i) { ra += sa[i]; rb += sb[i]; }
    __syncthreads();
    a = ra; b = rb;
}

// ---------------- generic 128x128x8 SGEMM with epilogue ----------------
// EPI 0: C = A*B + bias
// EPI 1: C = gelu(A*B + bias)
// EPI 2: C = A*B + bias + resid
template <int EPI>
__global__ void __launch_bounds__(256, 2) gemm_epi(
    const float* __restrict__ A, const float* __restrict__ B,
    const float* __restrict__ bias, const float* __restrict__ resid,
    float* __restrict__ C, int M, int N, int K)
{
    __shared__ float As[8][128];
    __shared__ float Bs[8][128];

    const int bm = blockIdx.y * 128;
    const int bn = blockIdx.x * 128;
    const int tid = threadIdx.x;

    const int a_row = tid >> 1;         // 0..127
    const int a_col = (tid & 1) * 4;    // 0 or 4
    const int b_row = tid >> 5;         // 0..7
    const int b_col = (tid & 31) * 4;   // 0..124

    const int tm = (tid >> 4) * 8;      // 0..120
    const int tn = (tid & 15) * 8;      // 0..120

    float acc[8][8];
    #pragma unroll
    for (int i = 0; i < 8; ++i)
        #pragma unroll
        for (int j = 0; j < 8; ++j) acc[i][j] = 0.0f;

    const float* Ap = A + (size_t)(bm + a_row) * K + a_col;
    const float* Bp = B + (size_t)b_row * N + bn + b_col;

    for (int k0 = 0; k0 < K; k0 += 8) {
        float4 av = *reinterpret_cast<const float4*>(Ap + k0);
        As[a_col + 0][a_row] = av.x;
        As[a_col + 1][a_row] = av.y;
        As[a_col + 2][a_row] = av.z;
        As[a_col + 3][a_row] = av.w;
        float4 bv4 = *reinterpret_cast<const float4*>(Bp + (size_t)k0 * N);
        *reinterpret_cast<float4*>(&Bs[b_row][b_col]) = bv4;
        __syncthreads();

        #pragma unroll
        for (int kk = 0; kk < 8; ++kk) {
            float ar[8], br[8];
            *reinterpret_cast<float4*>(ar)     = *reinterpret_cast<const float4*>(&As[kk][tm]);
            *reinterpret_cast<float4*>(ar + 4) = *reinterpret_cast<const float4*>(&As[kk][tm + 4]);
            *reinterpret_cast<float4*>(br)     = *reinterpret_cast<const float4*>(&Bs[kk][tn]);
            *reinterpret_cast<float4*>(br + 4) = *reinterpret_cast<const float4*>(&Bs[kk][tn + 4]);
            #pragma unroll
            for (int i = 0; i < 8; ++i)
                #pragma unroll
                for (int j = 0; j < 8; ++j)
                    acc[i][j] = fmaf(ar[i], br[j], acc[i][j]);
        }
        __syncthreads();
    }

    #pragma unroll
    for (int i = 0; i < 8; ++i) {
        const int row = bm + tm + i;
        #pragma unroll
        for (int j = 0; j < 8; ++j) {
            const int col = bn + tn + j;
            float v = acc[i][j] + bias[col];
            if (EPI == 1) v = gelu_exact(v);
            if (EPI == 2) v += resid[(size_t)row * N + col];
            acc[i][j] = v;
        }
        float* crow = C + (size_t)row * N + bn + tn;
        *reinterpret_cast<float4*>(crow)     = make_float4(acc[i][0], acc[i][1], acc[i][2], acc[i][3]);
        *reinterpret_cast<float4*>(crow + 4) = make_float4(acc[i][4], acc[i][5], acc[i][6], acc[i][7]);
    }
}

// ---------------- aff[b,h,c,p] = (1/8) * sum_d cores[h,c,d] * q[b,p,h*64+d] ----------------
// grid (PP/64, HH, BB), 256 threads. Tile: 64c x 64p, K=64 fully in smem.
__global__ void __launch_bounds__(256) aff_kernel(
    const float* __restrict__ q, const float* __restrict__ cores, float* __restrict__ aff)
{
    __shared__ float cs[64][65];   // [c][d]
    __shared__ float qs[64][65];   // [p][d]
    const int b = blockIdx.z, h = blockIdx.y, p0 = blockIdx.x * 64;
    const int tid = threadIdx.x;

    const int lr = tid >> 2;            // 0..63
    const int lc = (tid & 3) * 16;      // 0,16,32,48
    #pragma unroll
    for (int u = 0; u < 4; ++u) {
        float4 cv = *reinterpret_cast<const float4*>(cores + (size_t)(h * CC + lr) * HD_ + lc + u * 4);
        cs[lr][lc + u * 4 + 0] = cv.x; cs[lr][lc + u * 4 + 1] = cv.y;
        cs[lr][lc + u * 4 + 2] = cv.z; cs[lr][lc + u * 4 + 3] = cv.w;
        float4 qv = *reinterpret_cast<const float4*>(q + (size_t)(b * PP + p0 + lr) * DD + h * HD_ + lc + u * 4);
        qs[lr][lc + u * 4 + 0] = qv.x; qs[lr][lc + u * 4 + 1] = qv.y;
        qs[lr][lc + u * 4 + 2] = qv.z; qs[lr][lc + u * 4 + 3] = qv.w;
    }
    __syncthreads();

    const int c0 = (tid & 15) * 4;      // c
    const int pq = (tid >> 4) * 4;      // p
    float acc[4][4];
    #pragma unroll
    for (int i = 0; i < 4; ++i)
        #pragma unroll
        for (int j = 0; j < 4; ++j) acc[i][j] = 0.0f;

    #pragma unroll 8
    for (int k = 0; k < 64; ++k) {
        float cr[4], pr[4];
        #pragma unroll
        for (int i = 0; i < 4; ++i) cr[i] = cs[c0 + i][k];
        #pragma unroll
        for (int j = 0; j < 4; ++j) pr[j] = qs[pq + j][k];
        #pragma unroll
        for (int i = 0; i < 4; ++i)
            #pragma unroll
            for (int j = 0; j < 4; ++j) acc[i][j] = fmaf(cr[i], pr[j], acc[i][j]);
    }

    const size_t base = ((size_t)(b * HH + h) * CC) * PP;
    #pragma unroll
    for (int i = 0; i < 4; ++i) {
        float4 o = make_float4(acc[i][0] * 0.125f, acc[i][1] * 0.125f,
                               acc[i][2] * 0.125f, acc[i][3] * 0.125f);
        *reinterpret_cast<float4*>(aff + base + (size_t)(c0 + i) * PP + p0 + pq) = o;
    }
}

// ---------------- a_patch_to_core: softmax over cores (len 64) ----------------
// grid (BB*HH), 256 threads; p strided across threads (coalesced per c).
__global__ void __launch_bounds__(256) p2c_softmax(
    const float* __restrict__ aff, float* __restrict__ p2c)
{
    const size_t base = (size_t)blockIdx.x * CC * PP;
    const float* in = aff + base;
    float* out = p2c + base;
    for (int p = threadIdx.x; p < PP; p += 256) {
        float m = -1e30f, s = 0.0f;
        #pragma unroll
        for (int c = 0; c < CC; ++c) {
            float x = in[(size_t)c * PP + p];
            float nm = fmaxf(m, x);
            s = s * __expf(m - nm) + __expf(x - nm);
            m = nm;
        }
        const float inv = 1.0f / s;
        #pragma unroll
        for (int c = 0; c < CC; ++c)
            out[(size_t)c * PP + p] = __expf(in[(size_t)c * PP + p] - m) * inv;
    }
}

// ---------------- a_core_to_patch: softmax over patches (len 2048), in-place ----------------
// grid (BB*HH*CC), 256 threads; 8 values per thread, register-resident.
__global__ void __launch_bounds__(256) c2p_softmax(float* __restrict__ a)
{
    float* row = a + (size_t)blockIdx.x * PP;
    const int t = threadIdx.x;
    float x[8];
    *reinterpret_cast<float4*>(x)     = *reinterpret_cast<const float4*>(row + t * 8);
    *reinterpret_cast<float4*>(x + 4) = *reinterpret_cast<const float4*>(row + t * 8 + 4);
    float m = -1e30f;
    #pragma unroll
    for (int i = 0; i < 8; ++i) m = fmaxf(m, x[i]);
    m = blockReduceMax(m);
    float s = 0.0f;
    #pragma unroll
    for (int i = 0; i < 8; ++i) { x[i] = __expf(x[i] - m); s += x[i]; }
    s = blockReduceSum(s);
    const float inv = 1.0f / s;
    #pragma unroll
    for (int i = 0; i < 8; ++i) x[i] *= inv;
    *reinterpret_cast<float4*>(row + t * 8)     = *reinterpret_cast<float4*>(x);
    *reinterpret_cast<float4*>(row + t * 8 + 4) = *reinterpret_cast<float4*>(x + 4);
}

// ---------------- v_core[b,h,c,d] = sum_p input[b,p,h*64+d] * a_c2p[b,h,c,p] ----------------
// grid (HH, BB), 256 threads; K=2048 tiled by 64; smem stored k-major for float4 reads.
__global__ void __launch_bounds__(256) vcore_kernel(
    const float* __restrict__ input, const float* __restrict__ c2p, float* __restrict__ vcore)
{
    __shared__ float asT[64][68];  // [p][c]
    __shared__ float vs[64][68];   // [p][d]
    const int h = blockIdx.x, b = blockIdx.y;
    const int bh = b * HH + h;
    const float* abase = c2p + (size_t)bh * CC * PP;
    const int tid = threadIdx.x;
    const int lr = tid >> 2;            // row 0..63 (c for A, p for V)
    const int lc = (tid & 3) * 16;

    const int c0 = (tid & 15) * 4;
    const int d0 = (tid >> 4) * 4;
    float acc[4][4];
    #pragma unroll
    for (int i = 0; i < 4; ++i)
        #pragma unroll
        for (int j = 0; j < 4; ++j) acc[i][j] = 0.0f;

    for (int pt = 0; pt < PP; pt += 64) {
        #pragma unroll
        for (int u = 0; u < 4; ++u) {
            float4 av = *reinterpret_cast<const float4*>(abase + (size_t)lr * PP + pt + lc + u * 4);
            asT[lc + u * 4 + 0][lr] = av.x; asT[lc + u * 4 + 1][lr] = av.y;
            asT[lc + u * 4 + 2][lr] = av.z; asT[lc + u * 4 + 3][lr] = av.w;
            float4 vv = *reinterpret_cast<const float4*>(input + (size_t)(b * PP + pt + lr) * DD + h * HD_ + lc + u * 4);
            *reinterpret_cast<float4*>(&vs[lr][lc + u * 4]) = vv;
        }
        __syncthreads();
        #pragma unroll 16
        for (int k = 0; k < 64; ++k) {
            float4 ar = *reinterpret_cast<const float4*>(&asT[k][c0]);
            float4 vr = *reinterpret_cast<const float4*>(&vs[k][d0]);
            float arr[4] = {ar.x, ar.y, ar.z, ar.w};
            float vrr[4] = {vr.x, vr.y, vr.z, vr.w};
            #pragma unroll
            for (int i = 0; i < 4; ++i)
                #pragma unroll
                for (int j = 0; j < 4; ++j) acc[i][j] = fmaf(arr[i], vrr[j], acc[i][j]);
        }
        __syncthreads();
    }
    #pragma unroll
    for (int i = 0; i < 4; ++i) {
        float4 o = make_float4(acc[i][0], acc[i][1], acc[i][2], acc[i][3]);
        *reinterpret_cast<float4*>(vcore + (size_t)(bh * CC + c0 + i) * HD_ + d0) = o;
    }
}

// ---------------- v_patch + ffn_in concat ----------------
// v_patch[p,d] = sum_c v_core[c,d] * a_p2c[c,p]; write [input-vp, vp] into ffn_in.
// grid (PP/64, HH, BB), 256 threads.
__global__ void __launch_bounds__(256) vpatch_ffn_kernel(
    const float* __restrict__ input, const float* __restrict__ vcore,
    const float* __restrict__ p2c, float* __restrict__ ffn)
{
    __shared__ float vc[64][65];   // [c][d]
    __shared__ float ap[64][65];   // [c][p]
    const int b = blockIdx.z, h = blockIdx.y, p0 = blockIdx.x * 64;
    const int bh = b * HH + h;
    const int tid = threadIdx.x;
    const int lr = tid >> 2;
    const int lc = (tid & 3) * 16;

    #pragma unroll
    for (int u = 0; u < 4; ++u) {
        float4 cv = *reinterpret_cast<const float4*>(vcore + (size_t)(bh * CC + lr) * HD_ + lc + u * 4);
        vc[lr][lc + u * 4 + 0] = cv.x; vc[lr][lc + u * 4 + 1] = cv.y;
        vc[lr][lc + u * 4 + 2] = cv.z; vc[lr][lc + u * 4 + 3] = cv.w;
        float4 av = *reinterpret_cast<const float4*>(p2c + ((size_t)(bh * CC + lr)) * PP + p0 + lc + u * 4);
        ap[lr][lc + u * 4 + 0] = av.x; ap[lr][lc + u * 4 + 1] = av.y;
        ap[lr][lc + u * 4 + 2] = av.z; ap[lr][lc + u * 4 + 3] = av.w;
    }
    __syncthreads();

    const int pq = (tid >> 4) * 4;   // p
    const int d0 = (tid & 15) * 4;   // d
    float acc[4][4];
    #pragma unroll
    for (int i = 0; i < 4; ++i)
        #pragma unroll
        for (int j = 0; j < 4; ++j) acc[i][j] = 0.0f;

    #pragma unroll 8
    for (int k = 0; k < 64; ++k) {
        float apr[4], vcr[4];
        #pragma unroll
        for (int i = 0; i < 4; ++i) apr[i] = ap[k][pq + i];
        #pragma unroll
        for (int j = 0; j < 4; ++j) vcr[j] = vc[k][d0 + j];
        #pragma unroll
        for (int i = 0; i < 4; ++i)
            #pragma unroll
            for (int j = 0; j < 4; ++j) acc[i][j] = fmaf(apr[i], vcr[j], acc[i][j]);
    }

    #pragma unroll
    for (int i = 0; i < 4; ++i) {
        const int gp = b * PP + p0 + pq + i;
        float4 inp = *reinterpret_cast<const float4*>(input + (size_t)gp * DD + h * HD_ + d0);
        float4 vp = make_float4(acc[i][0], acc[i][1], acc[i][2], acc[i][3]);
        float4 diff = make_float4(inp.x - vp.x, inp.y - vp.y, inp.z - vp.z, inp.w - vp.w);
        float* fbase = ffn + (size_t)gp * FFNIN + h * HD_ + d0;
        *reinterpret_cast<float4*>(fbase) = diff;
        *reinterpret_cast<float4*>(fbase + DD) = vp;
    }
}

// ---------------- LayerNorm -> d_out ----------------
// grid MM, 128 threads, 4 floats/thread.
__global__ void __launch_bounds__(128) ln_kernel(
    const float* __restrict__ x, const float* __restrict__ gamma,
    const float* __restrict__ beta, float* __restrict__ out)
{
    const float* row = x + (size_t)blockIdx.x * DD;
    const int t = threadIdx.x;
    float4 v = *reinterpret_cast<const float4*>(row + t * 4);
    float s = v.x + v.y + v.z + v.w;
    float sq = v.x * v.x + v.y * v.y + v.z * v.z + v.w * v.w;
    blockReduceSum2(s, sq);
    const float mu = s * (1.0f / DD);
    const float var = sq * (1.0f / DD) - mu * mu;
    const float rstd = rsqrtf(var + 1e-5f);
    float4 g = *reinterpret_cast<const float4*>(gamma + t * 4);
    float4 bt = *reinterpret_cast<const float4*>(beta + t * 4);
    float4 o;
    o.x = (v.x - mu) * rstd * g.x + bt.x;
    o.y = (v.y - mu) * rstd * g.y + bt.y;
    o.z = (v.z - mu) * rstd * g.z + bt.z;
    o.w = (v.w - mu) * rstd * g.w + bt.w;
    *reinterpret_cast<float4*>(out + (size_t)blockIdx.x * DD + t * 4) = o;
}

// ---------------- launch ----------------
extern "C" void kernel_launch(void* const* d_in, const int* in_sizes, int n_in,
                              void* d_out, int out_size)
{
    (void)in_sizes; (void)n_in; (void)out_size;
    const float* input = (const float*)d_in[0];
    const float* cores = (const float*)d_in[1];
    const float* Wv    = (const float*)d_in[2];
    const float* bv    = (const float*)d_in[3];
    const float* W1    = (const float*)d_in[4];
    const float* b1    = (const float*)d_in[5];
    const float* W2    = (const float*)d_in[6];
    const float* b2    = (const float*)d_in[7];
    const float* gamma = (const float*)d_in[8];
    const float* beta  = (const float*)d_in[9];
    float* out = (float*)d_out;

    float *q, *aff, *p2c, *vcore, *ffn, *hid, *outp;
    cudaGetSymbolAddress((void**)&q,     g_q);
    cudaGetSymbolAddress((void**)&aff,   g_aff);
    cudaGetSymbolAddress((void**)&p2c,   g_p2c);
    cudaGetSymbolAddress((void**)&vcore, g_vcore);
    cudaGetSymbolAddress((void**)&ffn,   g_ffn);
    cudaGetSymbolAddress((void**)&hid,   g_hid);
    cudaGetSymbolAddress((void**)&outp,  g_outp);

    // 1. q = input @ Wv + bv
    gemm_epi<0><<<dim3(DD / 128, MM / 128), 256>>>(input, Wv, bv, nullptr, q, MM, DD, DD);
    // 2. aff
    aff_kernel<<<dim3(PP / 64, HH, BB), 256>>>(q, cores, aff);
    // 3a. softmax over cores -> p2c (reads aff before it is clobbered)
    p2c_softmax<<<BB * HH, 256>>>(aff, p2c);
    // 3b. softmax over patches, in place -> aff becomes a_core_to_patch
    c2p_softmax<<<BB * HH * CC, 256>>>(aff);
    // 4. v_core
    vcore_kernel<<<dim3(HH, BB), 256>>>(input, aff, vcore);
    // 5. v_patch + ffn_in concat
    vpatch_ffn_kernel<<<dim3(PP / 64, HH, BB), 256>>>(input, vcore, p2c, ffn);
    // 6. hid = gelu(ffn_in @ W1 + b1)
    gemm_epi<1><<<dim3(FFNHID / 128, MM / 128), 256>>>(ffn, W1, b1, nullptr, hid, MM, FFNHID, FFNIN);
    // 7. outp = input + hid @ W2 + b2
    gemm_epi<2><<<dim3(DD / 128, MM / 128), 256>>>(hid, W2, b2, input, outp, MM, DD, FFNHID);
    // 8. LayerNorm
    ln_kernel<<<MM, 128>>>(outp, gamma, beta, out);
}

// round 3
// speedup vs baseline: 2.5079x; 2.5079x over previous
#include <cuda_runtime.h>
#include <cuda_bf16.h>
#include <math.h>
#include <stdint.h>

// ---------------- problem constants ----------------
#define BB      16
#define PP      2048
#define DD      512
#define HH      8
#define CC      64
#define HD_     64
#define MM      (BB * PP)        // 32768
#define FFNIN   1024
#define FFNHID  4096

// ---------------- scratch (device globals; allocation-free) ----------------
__device__ __align__(256) float g_q[MM * DD];
__device__ __align__(256) float g_aff[BB * HH * CC * PP];
__device__ __align__(256) float g_p2c[BB * HH * CC * PP];
__device__ __align__(256) float g_vcore[BB * HH * CC * HD_];
__device__ __align__(256) float g_outp[MM * DD];

__device__ __align__(256) __nv_bfloat16 g_in_hi[MM * DD];
__device__ __align__(256) __nv_bfloat16 g_in_lo[MM * DD];
__device__ __align__(256) __nv_bfloat16 g_ffn_hi[MM * FFNIN];
__device__ __align__(256) __nv_bfloat16 g_ffn_lo[MM * FFNIN];
__device__ __align__(256) __nv_bfloat16 g_hid_hi[(size_t)MM * FFNHID];
__device__ __align__(256) __nv_bfloat16 g_hid_lo[(size_t)MM * FFNHID];
// weights transposed to [N][K]
__device__ __align__(256) __nv_bfloat16 g_wvT_hi[DD * DD];
__device__ __align__(256) __nv_bfloat16 g_wvT_lo[DD * DD];
__device__ __align__(256) __nv_bfloat16 g_w1T_hi[FFNHID * FFNIN];
__device__ __align__(256) __nv_bfloat16 g_w1T_lo[FFNHID * FFNIN];
__device__ __align__(256) __nv_bfloat16 g_w2T_hi[DD * FFNHID];
__device__ __align__(256) __nv_bfloat16 g_w2T_lo[DD * FFNHID];

// ---------------- PTX helpers (sm_80-era instructions only) ----------------
__device__ __forceinline__ uint32_t smem_u32(const void* p) {
    uint32_t a;
    asm("{ .reg .u64 t; cvta.to.shared.u64 t, %1; cvt.u32.u64 %0, t; }" : "=r"(a) : "l"(p));
    return a;
}
__device__ __forceinline__ void cp16(uint32_t s, const void* g) {
    asm volatile("cp.async.cg.shared.global [%0], [%1], 16;" :: "r"(s), "l"(g));
}
__device__ __forceinline__ void ldm_x4(uint32_t* r, uint32_t addr) {
    asm volatile("ldmatrix.sync.aligned.m8n8.x4.shared.b16 {%0,%1,%2,%3}, [%4];"
                 : "=r"(r[0]), "=r"(r[1]), "=r"(r[2]), "=r"(r[3]) : "r"(addr));
}
__device__ __forceinline__ void mma_bf16(float* d, const uint32_t* a, const uint32_t* b) {
    asm volatile(
        "mma.sync.aligned.m16n8k16.row.col.f32.bf16.bf16.f32 "
        "{%0,%1,%2,%3}, {%4,%5,%6,%7}, {%8,%9}, {%0,%1,%2,%3};"
        : "+f"(d[0]), "+f"(d[1]), "+f"(d[2]), "+f"(d[3])
        : "r"(a[0]), "r"(a[1]), "r"(a[2]), "r"(a[3]), "r"(b[0]), "r"(b[1]));
}

__device__ __forceinline__ float gelu_exact(float x) {
    return 0.5f * x * (1.0f + erff(x * 0.7071067811865476f));
}

// ---------------- bf16x3 GEMM via mma.sync, BM=128 BN=128 BK=32 ----------------
// EPI 0: Cf = D + bias                       (fp32 out)
// EPI 1: (Ch,Cl) = split(gelu(D + bias))     (bf16 hi/lo out)
// EPI 2: Cf = D + bias + resid               (fp32 out)
#define BKK       32
#define RSTRIDE   40                        // bf16 elements per smem row (32 + 8 pad)
#define TILE_B    (128 * RSTRIDE * 2)       // 10240 bytes per matrix tile
#define STAGE_B   (4 * TILE_B)              // Ahi, Alo, Bhi, Blo = 40960
#define GEMM_SMEM (2 * STAGE_B)             // 81920

template <int EPI>
__global__ void __launch_bounds__(256, 2) gemm_mma(
    const __nv_bfloat16* __restrict__ Ah, const __nv_bfloat16* __restrict__ Al,
    const __nv_bfloat16* __restrict__ Bh, const __nv_bfloat16* __restrict__ Bl,
    const float* __restrict__ bias, const float* __restrict__ resid,
    float* __restrict__ Cf, __nv_bfloat16* __restrict__ Ch, __nv_bfloat16* __restrict__ Cl,
    int N, int K)
{
    extern __shared__ __align__(256) char smem[];
    const uint32_t sb = smem_u32(smem);

    const int tid = threadIdx.x;
    const int wid = tid >> 5;
    const int lane = tid & 31;
    const int bm = blockIdx.y * 128;
    const int bn = blockIdx.x * 128;
    const int mOff = (wid & 3) * 32;
    const int nOff = (wid >> 2) * 64;

    // per-thread ldmatrix source row/col selectors
    const int aRow = lane & 15;
    const int aCol = (lane >> 4) * 8;
    const int bRow = (lane & 7) + ((lane >> 4) << 3);
    const int bCol = ((lane >> 3) & 1) * 8;

    float acc[2][8][4];
    #pragma unroll
    for (int i = 0; i < 2; ++i)
        #pragma unroll
        for (int j = 0; j < 8; ++j)
            #pragma unroll
            for (int k = 0; k < 4; ++k) acc[i][j][k] = 0.0f;

    const int nch = K / BKK;

    // stage loader: 2 chunks of 16B per thread per matrix
    auto loadStage = [&](int s, int it) {
        const int k0 = it * BKK;
        const uint32_t st = sb + s * STAGE_B;
        #pragma unroll
        for (int i = 0; i < 2; ++i) {
            const int id = tid + i * 256;
            const int r = id >> 2, c = id & 3;
            const uint32_t so = (uint32_t)(r * (RSTRIDE * 2) + c * 16);
            const size_t goa = (size_t)(bm + r) * K + k0 + c * 8;
            const size_t gob = (size_t)(bn + r) * K + k0 + c * 8;
            cp16(st + so,              Ah + goa);
            cp16(st + TILE_B + so,     Al + goa);
            cp16(st + 2 * TILE_B + so, Bh + gob);
            cp16(st + 3 * TILE_B + so, Bl + gob);
        }
        asm volatile("cp.async.commit_group;" ::: "memory");
    };

    loadStage(0, 0);

    for (int it = 0; it < nch; ++it) {
        const int s = it & 1;
        if (it + 1 < nch) {
            loadStage(s ^ 1, it + 1);
            asm volatile("cp.async.wait_group 1;" ::: "memory");
        } else {
            asm volatile("cp.async.wait_group 0;" ::: "memory");
        }
        __syncthreads();

        const uint32_t st = sb + s * STAGE_B;
        const uint32_t pa[3] = {st, st, st + TILE_B};                       // Ah, Ah, Al
        const uint32_t pb[3] = {st + 2 * TILE_B, st + 3 * TILE_B, st + 2 * TILE_B};  // Bh, Bl, Bh

        #pragma unroll
        for (int pass = 0; pass < 3; ++pass) {
            #pragma unroll
            for (int kk = 0; kk < 2; ++kk) {
                uint32_t a[2][4];
                #pragma unroll
                for (int mf = 0; mf < 2; ++mf)
                    ldm_x4(a[mf], pa[pass] +
                        (uint32_t)(((mOff + mf * 16 + aRow) * RSTRIDE + kk * 16 + aCol) * 2));
                uint32_t b[4][4];
                #pragma unroll
                for (int n2 = 0; n2 < 4; ++n2)
                    ldm_x4(b[n2], pb[pass] +
                        (uint32_t)(((nOff + n2 * 16 + bRow) * RSTRIDE + kk * 16 + bCol) * 2));
                #pragma unroll
                for (int mf = 0; mf < 2; ++mf)
                    #pragma unroll
                    for (int nf = 0; nf < 8; ++nf)
                        mma_bf16(acc[mf][nf], a[mf], &b[nf >> 1][(nf & 1) * 2]);
            }
        }
        __syncthreads();
    }

    // ---- epilogue ----
    #pragma unroll
    for (int mf = 0; mf < 2; ++mf) {
        #pragma unroll
        for (int half = 0; half < 2; ++half) {
            const int row = bm + mOff + mf * 16 + (lane >> 2) + half * 8;
            #pragma unroll
            for (int nf = 0; nf < 8; ++nf) {
                const int col = bn + nOff + nf * 8 + (lane & 3) * 2;
                float v0 = acc[mf][nf][half * 2 + 0] + bias[col];
                float v1 = acc[mf][nf][half * 2 + 1] + bias[col + 1];
                if (EPI == 1) {
                    v0 = gelu_exact(v0);
                    v1 = gelu_exact(v1);
                    __nv_bfloat16 h0 = __float2bfloat16(v0);
                    __nv_bfloat16 h1 = __float2bfloat16(v1);
                    __nv_bfloat16 l0 = __float2bfloat16(v0 - __bfloat162float(h0));
                    __nv_bfloat16 l1 = __float2bfloat16(v1 - __bfloat162float(h1));
                    uint32_t hp = (uint32_t)__bfloat16_as_ushort(h0) |
                                  ((uint32_t)__bfloat16_as_ushort(h1) << 16);
                    uint32_t lp = (uint32_t)__bfloat16_as_ushort(l0) |
                                  ((uint32_t)__bfloat16_as_ushort(l1) << 16);
                    *reinterpret_cast<uint32_t*>(Ch + (size_t)row * N + col) = hp;
                    *reinterpret_cast<uint32_t*>(Cl + (size_t)row * N + col) = lp;
                } else {
                    if (EPI == 2) {
                        const float* rp = resid + (size_t)row * N + col;
                        v0 += rp[0];
                        v1 += rp[1];
                    }
                    *reinterpret_cast<float2*>(Cf + (size_t)row * N + col) = make_float2(v0, v1);
                }
            }
        }
    }
}

// ---------------- fp32 -> bf16 hi/lo split (elementwise) ----------------
__global__ void __launch_bounds__(256) split_kernel(
    const float* __restrict__ x, __nv_bfloat16* __restrict__ h, __nv_bfloat16* __restrict__ l, int n4)
{
    int i = blockIdx.x * 256 + threadIdx.x;
    if (i >= n4) return;
    float4 v = reinterpret_cast<const float4*>(x)[i];
    __nv_bfloat16 h0 = __float2bfloat16(v.x), h1 = __float2bfloat16(v.y);
    __nv_bfloat16 h2 = __float2bfloat16(v.z), h3 = __float2bfloat16(v.w);
    __nv_bfloat16 l0 = __float2bfloat16(v.x - __bfloat162float(h0));
    __nv_bfloat16 l1 = __float2bfloat16(v.y - __bfloat162float(h1));
    __nv_bfloat16 l2 = __float2bfloat16(v.z - __bfloat162float(h2));
    __nv_bfloat16 l3 = __float2bfloat16(v.w - __bfloat162float(h3));
    __nv_bfloat16 hb[4] = {h0, h1, h2, h3}, lb[4] = {l0, l1, l2, l3};
    reinterpret_cast<uint2*>(h)[i] = *reinterpret_cast<const uint2*>(hb);
    reinterpret_cast<uint2*>(l)[i] = *reinterpret_cast<const uint2*>(lb);
}

// ---------------- W[K][N] fp32 -> Wt[N][K] bf16 hi/lo ----------------
__global__ void __launch_bounds__(256) transpose_split(
    const float* __restrict__ W, __nv_bfloat16* __restrict__ Th, __nv_bfloat16* __restrict__ Tl,
    int K, int N)
{
    __shared__ float s[32][33];
    const int n0 = blockIdx.x * 32, k0 = blockIdx.y * 32;
    const int c = threadIdx.x & 31, r0 = threadIdx.x >> 5;
    #pragma unroll
    for (int r = r0; r < 32; r += 8)
        s[r][c] = W[(size_t)(k0 + r) * N + n0 + c];
    __syncthreads();
    #pragma unroll
    for (int r = r0; r < 32; r += 8) {
        float v = s[c][r];  // = W[k0+c][n0+r]
        __nv_bfloat16 h = __float2bfloat16(v);
        Th[(size_t)(n0 + r) * K + k0 + c] = h;
        Tl[(size_t)(n0 + r) * K + k0 + c] = __float2bfloat16(v - __bfloat162float(h));
    }
}

// ---------------- block reduce helpers ----------------
__device__ __forceinline__ float blockReduceMax(float v) {
    __shared__ float sm[8];
    #pragma unroll
    for (int o = 16; o > 0; o >>= 1) v = fmaxf(v, __shfl_xor_sync(0xffffffffu, v, o));
    int wid = threadIdx.x >> 5, nw = blockDim.x >> 5;
    if ((threadIdx.x & 31) == 0) sm[wid] = v;
    __syncthreads();
    float r = -1e30f;
    for (int i = 0; i < nw; ++i) r = fmaxf(r, sm[i]);
    __syncthreads();
    return r;
}
__device__ __forceinline__ float blockReduceSum(float v) {
    __shared__ float sm[8];
    #pragma unroll
    for (int o = 16; o > 0; o >>= 1) v += __shfl_xor_sync(0xffffffffu, v, o);
    int wid = threadIdx.x >> 5, nw = blockDim.x >> 5;
    if ((threadIdx.x & 31) == 0) sm[wid] = v;
    __syncthreads();
    float r = 0.0f;
    for (int i = 0; i < nw; ++i) r += sm[i];
    __syncthreads();
    return r;
}
__device__ __forceinline__ void blockReduceSum2(float& a, float& b) {
    __shared__ float sa[8], sb[8];
    #pragma unroll
    for (int o = 16; o > 0; o >>= 1) {
        a += __shfl_xor_sync(0xffffffffu, a, o);
        b += __shfl_xor_sync(0xffffffffu, b, o);
    }
    int wid = threadIdx.x >> 5, nw = blockDim.x >> 5;
    if ((threadIdx.x & 31) == 0) { sa[wid] = a; sb[wid] = b; }
    __syncthreads();
    float ra = 0.0f, rb = 0.0f;
    for (int i = 0; i < nw; ++i) { ra += sa[i]; rb += sb[i]; }
    __syncthreads();
    a = ra; b = rb;
}

// ---------------- aff[b,h,c,p] = (1/8) * sum_d cores[h,c,d] * q[b,p,h*64+d] ----------------
__global__ void __launch_bounds__(256) aff_kernel(
    const float* __restrict__ q, const float* __restrict__ cores, float* __restrict__ aff)
{
    __shared__ float cs[64][65];
    __shared__ float qs[64][65];
    const int b = blockIdx.z, h = blockIdx.y, p0 = blockIdx.x * 64;
    const int tid = threadIdx.x;
    const int lr = tid >> 2;
    const int lc = (tid & 3) * 16;
    #pragma unroll
    for (int u = 0; u < 4; ++u) {
        float4 cv = *reinterpret_cast<const float4*>(cores + (size_t)(h * CC + lr) * HD_ + lc + u * 4);
        cs[lr][lc + u * 4 + 0] = cv.x; cs[lr][lc + u * 4 + 1] = cv.y;
        cs[lr][lc + u * 4 + 2] = cv.z; cs[lr][lc + u * 4 + 3] = cv.w;
        float4 qv = *reinterpret_cast<const float4*>(q + (size_t)(b * PP + p0 + lr) * DD + h * HD_ + lc + u * 4);
        qs[lr][lc + u * 4 + 0] = qv.x; qs[lr][lc + u * 4 + 1] = qv.y;
        qs[lr][lc + u * 4 + 2] = qv.z; qs[lr][lc + u * 4 + 3] = qv.w;
    }
    __syncthreads();
    const int c0 = (tid & 15) * 4;
    const int pq = (tid >> 4) * 4;
    float acc[4][4];
    #pragma unroll
    for (int i = 0; i < 4; ++i)
        #pragma unroll
        for (int j = 0; j < 4; ++j) acc[i][j] = 0.0f;
    #pragma unroll 8
    for (int k = 0; k < 64; ++k) {
        float cr[4], pr[4];
        #pragma unroll
        for (int i = 0; i < 4; ++i) cr[i] = cs[c0 + i][k];
        #pragma unroll
        for (int j = 0; j < 4; ++j) pr[j] = qs[pq + j][k];
        #pragma unroll
        for (int i = 0; i < 4; ++i)
            #pragma unroll
            for (int j = 0; j < 4; ++j) acc[i][j] = fmaf(cr[i], pr[j], acc[i][j]);
    }
    const size_t base = ((size_t)(b * HH + h) * CC) * PP;
    #pragma unroll
    for (int i = 0; i < 4; ++i) {
        float4 o = make_float4(acc[i][0] * 0.125f, acc[i][1] * 0.125f,
                               acc[i][2] * 0.125f, acc[i][3] * 0.125f);
        *reinterpret_cast<float4*>(aff + base + (size_t)(c0 + i) * PP + p0 + pq) = o;
    }
}

// ---------------- softmax over cores ----------------
__global__ void __launch_bounds__(256) p2c_softmax(
    const float* __restrict__ aff, float* __restrict__ p2c)
{
    const size_t base = (size_t)blockIdx.x * CC * PP;
    const float* in = aff + base;
    float* out = p2c + base;
    for (int p = threadIdx.x; p < PP; p += 256) {
        float m = -1e30f, s = 0.0f;
        #pragma unroll
        for (int c = 0; c < CC; ++c) {
            float x = in[(size_t)c * PP + p];
            float nm = fmaxf(m, x);
            s = s * __expf(m - nm) + __expf(x - nm);
            m = nm;
        }
        const float inv = 1.0f / s;
        #pragma unroll
        for (int c = 0; c < CC; ++c)
            out[(size_t)c * PP + p] = __expf(in[(size_t)c * PP + p] - m) * inv;
    }
}

// ---------------- softmax over patches (in-place) ----------------
__global__ void __launch_bounds__(256) c2p_softmax(float* __restrict__ a)
{
    float* row = a + (size_t)blockIdx.x * PP;
    const int t = threadIdx.x;
    float x[8];
    *reinterpret_cast<float4*>(x)     = *reinterpret_cast<const float4*>(row + t * 8);
    *reinterpret_cast<float4*>(x + 4) = *reinterpret_cast<const float4*>(row + t * 8 + 4);
    float m = -1e30f;
    #pragma unroll
    for (int i = 0; i < 8; ++i) m = fmaxf(m, x[i]);
    m = blockReduceMax(m);
    float s = 0.0f;
    #pragma unroll
    for (int i = 0; i < 8; ++i) { x[i] = __expf(x[i] - m); s += x[i]; }
    s = blockReduceSum(s);
    const float inv = 1.0f / s;
    #pragma unroll
    for (int i = 0; i < 8; ++i) x[i] *= inv;
    *reinterpret_cast<float4*>(row + t * 8)     = *reinterpret_cast<float4*>(x);
    *reinterpret_cast<float4*>(row + t * 8 + 4) = *reinterpret_cast<float4*>(x + 4);
}

// ---------------- v_core ----------------
__global__ void __launch_bounds__(256) vcore_kernel(
    const float* __restrict__ input, const float* __restrict__ c2p, float* __restrict__ vcore)
{
    __shared__ float asT[64][68];
    __shared__ float vs[64][68];
    const int h = blockIdx.x, b = blockIdx.y;
    const int bh = b * HH + h;
    const float* abase = c2p + (size_t)bh * CC * PP;
    const int tid = threadIdx.x;
    const int lr = tid >> 2;
    const int lc = (tid & 3) * 16;
    const int c0 = (tid & 15) * 4;
    const int d0 = (tid >> 4) * 4;
    float acc[4][4];
    #pragma unroll
    for (int i = 0; i < 4; ++i)
        #pragma unroll
        for (int j = 0; j < 4; ++j) acc[i][j] = 0.0f;

    for (int pt = 0; pt < PP; pt += 64) {
        #pragma unroll
        for (int u = 0; u < 4; ++u) {
            float4 av = *reinterpret_cast<const float4*>(abase + (size_t)lr * PP + pt + lc + u * 4);
            asT[lc + u * 4 + 0][lr] = av.x; asT[lc + u * 4 + 1][lr] = av.y;
            asT[lc + u * 4 + 2][lr] = av.z; asT[lc + u * 4 + 3][lr] = av.w;
            float4 vv = *reinterpret_cast<const float4*>(input + (size_t)(b * PP + pt + lr) * DD + h * HD_ + lc + u * 4);
            *reinterpret_cast<float4*>(&vs[lr][lc + u * 4]) = vv;
        }
        __syncthreads();
        #pragma unroll 16
        for (int k = 0; k < 64; ++k) {
            float4 ar = *reinterpret_cast<const float4*>(&asT[k][c0]);
            float4 vr = *reinterpret_cast<const float4*>(&vs[k][d0]);
            float arr[4] = {ar.x, ar.y, ar.z, ar.w};
            float vrr[4] = {vr.x, vr.y, vr.z, vr.w};
            #pragma unroll
            for (int i = 0; i < 4; ++i)
                #pragma unroll
                for (int j = 0; j < 4; ++j) acc[i][j] = fmaf(arr[i], vrr[j], acc[i][j]);
        }
        __syncthreads();
    }
    #pragma unroll
    for (int i = 0; i < 4; ++i) {
        float4 o = make_float4(acc[i][0], acc[i][1], acc[i][2], acc[i][3]);
        *reinterpret_cast<float4*>(vcore + (size_t)(bh * CC + c0 + i) * HD_ + d0) = o;
    }
}

// ---------------- v_patch + ffn_in concat (writes bf16 hi/lo) ----------------
__device__ __forceinline__ void split_store4(__nv_bfloat16* ph, __nv_bfloat16* pl, float4 v) {
    __nv_bfloat16 h0 = __float2bfloat16(v.x), h1 = __float2bfloat16(v.y);
    __nv_bfloat16 h2 = __float2bfloat16(v.z), h3 = __float2bfloat16(v.w);
    __nv_bfloat16 l0 = __float2bfloat16(v.x - __bfloat162float(h0));
    __nv_bfloat16 l1 = __float2bfloat16(v.y - __bfloat162float(h1));
    __nv_bfloat16 l2 = __float2bfloat16(v.z - __bfloat162float(h2));
    __nv_bfloat16 l3 = __float2bfloat16(v.w - __bfloat162float(h3));
    __nv_bfloat16 hb[4] = {h0, h1, h2, h3}, lb[4] = {l0, l1, l2, l3};
    *reinterpret_cast<uint2*>(ph) = *reinterpret_cast<const uint2*>(hb);
    *reinterpret_cast<uint2*>(pl) = *reinterpret_cast<const uint2*>(lb);
}

__global__ void __launch_bounds__(256) vpatch_ffn_kernel(
    const float* __restrict__ input, const float* __restrict__ vcore,
    const float* __restrict__ p2c,
    __nv_bfloat16* __restrict__ fh, __nv_bfloat16* __restrict__ fl)
{
    __shared__ float vc[64][65];
    __shared__ float ap[64][65];
    const int b = blockIdx.z, h = blockIdx.y, p0 = blockIdx.x * 64;
    const int bh = b * HH + h;
    const int tid = threadIdx.x;
    const int lr = tid >> 2;
    const int lc = (tid & 3) * 16;
    #pragma unroll
    for (int u = 0; u < 4; ++u) {
        float4 cv = *reinterpret_cast<const float4*>(vcore + (size_t)(bh * CC + lr) * HD_ + lc + u * 4);
        vc[lr][lc + u * 4 + 0] = cv.x; vc[lr][lc + u * 4 + 1] = cv.y;
        vc[lr][lc + u * 4 + 2] = cv.z; vc[lr][lc + u * 4 + 3] = cv.w;
        float4 av = *reinterpret_cast<const float4*>(p2c + ((size_t)(bh * CC + lr)) * PP + p0 + lc + u * 4);
        ap[lr][lc + u * 4 + 0] = av.x; ap[lr][lc + u * 4 + 1] = av.y;
        ap[lr][lc + u * 4 + 2] = av.z; ap[lr][lc + u * 4 + 3] = av.w;
    }
    __syncthreads();
    const int pq = (tid >> 4) * 4;
    const int d0 = (tid & 15) * 4;
    float acc[4][4];
    #pragma unroll
    for (int i = 0; i < 4; ++i)
        #pragma unroll
        for (int j = 0; j < 4; ++j) acc[i][j] = 0.0f;
    #pragma unroll 8
    for (int k = 0; k < 64; ++k) {
        float apr[4], vcr[4];
        #pragma unroll
        for (int i = 0; i < 4; ++i) apr[i] = ap[k][pq + i];
        #pragma unroll
        for (int j = 0; j < 4; ++j) vcr[j] = vc[k][d0 + j];
        #pragma unroll
        for (int i = 0; i < 4; ++i)
            #pragma unroll
            for (int j = 0; j < 4; ++j) acc[i][j] = fmaf(apr[i], vcr[j], acc[i][j]);
    }
    #pragma unroll
    for (int i = 0; i < 4; ++i) {
        const int gp = b * PP + p0 + pq + i;
        float4 inp = *reinterpret_cast<const float4*>(input + (size_t)gp * DD + h * HD_ + d0);
        float4 vp = make_float4(acc[i][0], acc[i][1], acc[i][2], acc[i][3]);
        float4 diff = make_float4(inp.x - vp.x, inp.y - vp.y, inp.z - vp.z, inp.w - vp.w);
        const size_t fo = (size_t)gp * FFNIN + h * HD_ + d0;
        split_store4(fh + fo, fl + fo, diff);
        split_store4(fh + fo + DD, fl + fo + DD, vp);
    }
}

// ---------------- LayerNorm ----------------
__global__ void __launch_bounds__(128) ln_kernel(
    const float* __restrict__ x, const float* __restrict__ gamma,
    const float* __restrict__ beta, float* __restrict__ out)
{
    const float* row = x + (size_t)blockIdx.x * DD;
    const int t = threadIdx.x;
    float4 v = *reinterpret_cast<const float4*>(row + t * 4);
    float s = v.x + v.y + v.z + v.w;
    float sq = v.x * v.x + v.y * v.y + v.z * v.z + v.w * v.w;
    blockReduceSum2(s, sq);
    const float mu = s * (1.0f / DD);
    const float var = sq * (1.0f / DD) - mu * mu;
    const float rstd = rsqrtf(var + 1e-5f);
    float4 g = *reinterpret_cast<const float4*>(gamma + t * 4);
    float4 bt = *reinterpret_cast<const float4*>(beta + t * 4);
    float4 o;
    o.x = (v.x - mu) * rstd * g.x + bt.x;
    o.y = (v.y - mu) * rstd * g.y + bt.y;
    o.z = (v.z - mu) * rstd * g.z + bt.z;
    o.w = (v.w - mu) * rstd * g.w + bt.w;
    *reinterpret_cast<float4*>(out + (size_t)blockIdx.x * DD + t * 4) = o;
}

// ---------------- launch ----------------
extern "C" void kernel_launch(void* const* d_in, const int* in_sizes, int n_in,
                              void* d_out, int out_size)
{
    (void)in_sizes; (void)n_in; (void)out_size;
    const float* input = (const float*)d_in[0];
    const float* cores = (const float*)d_in[1];
    const float* Wv    = (const float*)d_in[2];
    const float* bv    = (const float*)d_in[3];
    const float* W1    = (const float*)d_in[4];
    const float* b1    = (const float*)d_in[5];
    const float* W2    = (const float*)d_in[6];
    const float* b2    = (const float*)d_in[7];
    const float* gamma = (const float*)d_in[8];
    const float* beta  = (const float*)d_in[9];
    float* out = (float*)d_out;

    float *q, *aff, *p2c, *vcore, *outp;
    __nv_bfloat16 *in_hi, *in_lo, *ffn_hi, *ffn_lo, *hid_hi, *hid_lo;
    __nv_bfloat16 *wvT_hi, *wvT_lo, *w1T_hi, *w1T_lo, *w2T_hi, *w2T_lo;
    cudaGetSymbolAddress((void**)&q, g_q);
    cudaGetSymbolAddress((void**)&aff, g_aff);
    cudaGetSymbolAddress((void**)&p2c, g_p2c);
    cudaGetSymbolAddress((void**)&vcore, g_vcore);
    cudaGetSymbolAddress((void**)&outp, g_outp);
    cudaGetSymbolAddress((void**)&in_hi, g_in_hi);
    cudaGetSymbolAddress((void**)&in_lo, g_in_lo);
    cudaGetSymbolAddress((void**)&ffn_hi, g_ffn_hi);
    cudaGetSymbolAddress((void**)&ffn_lo, g_ffn_lo);
    cudaGetSymbolAddress((void**)&hid_hi, g_hid_hi);
    cudaGetSymbolAddress((void**)&hid_lo, g_hid_lo);
    cudaGetSymbolAddress((void**)&wvT_hi, g_wvT_hi);
    cudaGetSymbolAddress((void**)&wvT_lo, g_wvT_lo);
    cudaGetSymbolAddress((void**)&w1T_hi, g_w1T_hi);
    cudaGetSymbolAddress((void**)&w1T_lo, g_w1T_lo);
    cudaGetSymbolAddress((void**)&w2T_hi, g_w2T_hi);
    cudaGetSymbolAddress((void**)&w2T_lo, g_w2T_lo);

    cudaFuncSetAttribute(gemm_mma<0>, cudaFuncAttributeMaxDynamicSharedMemorySize, GEMM_SMEM);
    cudaFuncSetAttribute(gemm_mma<1>, cudaFuncAttributeMaxDynamicSharedMemorySize, GEMM_SMEM);
    cudaFuncSetAttribute(gemm_mma<2>, cudaFuncAttributeMaxDynamicSharedMemorySize, GEMM_SMEM);

    // prep: splits + weight transposes
    split_kernel<<<(MM * DD / 4 + 255) / 256, 256>>>(input, in_hi, in_lo, MM * DD / 4);
    transpose_split<<<dim3(DD / 32, DD / 32), 256>>>(Wv, wvT_hi, wvT_lo, DD, DD);
    transpose_split<<<dim3(FFNHID / 32, FFNIN / 32), 256>>>(W1, w1T_hi, w1T_lo, FFNIN, FFNHID);
    transpose_split<<<dim3(DD / 32, FFNHID / 32), 256>>>(W2, w2T_hi, w2T_lo, FFNHID, DD);

    // 1. q = input @ Wv + bv
    gemm_mma<0><<<dim3(DD / 128, MM / 128), 256, GEMM_SMEM>>>(
        in_hi, in_lo, wvT_hi, wvT_lo, bv, nullptr, q, nullptr, nullptr, DD, DD);
    // 2-5. affinity + dual softmax + aggregate + redistribute
    aff_kernel<<<dim3(PP / 64, HH, BB), 256>>>(q, cores, aff);
    p2c_softmax<<<BB * HH, 256>>>(aff, p2c);
    c2p_softmax<<<BB * HH * CC, 256>>>(aff);
    vcore_kernel<<<dim3(HH, BB), 256>>>(input, aff, vcore);
    vpatch_ffn_kernel<<<dim3(PP / 64, HH, BB), 256>>>(input, vcore, p2c, ffn_hi, ffn_lo);
    // 6. hid = gelu(ffn @ W1 + b1)   (bf16 hi/lo out)
    gemm_mma<1><<<dim3(FFNHID / 128, MM / 128), 256, GEMM_SMEM>>>(
        ffn_hi, ffn_lo, w1T_hi, w1T_lo, b1, nullptr, nullptr, hid_hi, hid_lo, FFNHID, FFNIN);
    // 7. outp = input + hid @ W2 + b2
    gemm_mma<2><<<dim3(DD / 128, MM / 128), 256, GEMM_SMEM>>>(
        hid_hi, hid_lo, w2T_hi, w2T_lo, b2, input, outp, nullptr, nullptr, DD, FFNHID);
    // 8. LayerNorm
    ln_kernel<<<MM, 128>>>(outp, gamma, beta, out);
}

// round 5
// speedup vs baseline: 3.5779x; 1.4266x over previous
#include <cuda_runtime.h>
#include <cuda_fp16.h>
#include <math.h>
#include <stdint.h>

// ---------------- problem constants ----------------
#define BB      16
#define PP      2048
#define DD      512
#define HH      8
#define CC      64
#define HD_     64
#define MM      (BB * PP)        // 32768
#define FFNIN   1024
#define FFNHID  4096

// ---------------- scratch (device globals; allocation-free) ----------------
__device__ __align__(256) float g_q[MM * DD];
__device__ __align__(256) float g_aff[BB * HH * CC * PP];
__device__ __align__(256) float g_p2c[BB * HH * CC * PP];
__device__ __align__(256) float g_vcore[BB * HH * CC * HD_];
__device__ __align__(256) float g_outp[MM * DD];

__device__ __align__(256) __half g_in_hi[MM * DD];
__device__ __align__(256) __half g_in_lo[MM * DD];
__device__ __align__(256) __half g_ffn_hi[MM * FFNIN];
__device__ __align__(256) __half g_ffn_lo[MM * FFNIN];
__device__ __align__(256) __half g_hid_hi[(size_t)MM * FFNHID];
__device__ __align__(256) __half g_hid_lo[(size_t)MM * FFNHID];
// weights transposed to [N][K], fp16 hi only (B-side)
__device__ __align__(256) __half g_wvT[DD * DD];
__device__ __align__(256) __half g_w1T[FFNHID * FFNIN];
__device__ __align__(256) __half g_w2T[DD * FFNHID];

// ---------------- PTX helpers (sm_80-era instructions only) ----------------
__device__ __forceinline__ uint32_t smem_u32(const void* p) {
    uint32_t a;
    asm("{ .reg .u64 t; cvta.to.shared.u64 t, %1; cvt.u32.u64 %0, t; }" : "=r"(a) : "l"(p));
    return a;
}
__device__ __forceinline__ void cp16(uint32_t s, const void* g) {
    asm volatile("cp.async.cg.shared.global [%0], [%1], 16;" :: "r"(s), "l"(g));
}
__device__ __forceinline__ void ldm_x4(uint32_t* r, uint32_t addr) {
    asm volatile("ldmatrix.sync.aligned.m8n8.x4.shared.b16 {%0,%1,%2,%3}, [%4];"
                 : "=r"(r[0]), "=r"(r[1]), "=r"(r[2]), "=r"(r[3]) : "r"(addr));
}
__device__ __forceinline__ void mma_f16(float* d, const uint32_t* a, const uint32_t* b) {
    asm volatile(
        "mma.sync.aligned.m16n8k16.row.col.f32.f16.f16.f32 "
        "{%0,%1,%2,%3}, {%4,%5,%6,%7}, {%8,%9}, {%0,%1,%2,%3};"
        : "+f"(d[0]), "+f"(d[1]), "+f"(d[2]), "+f"(d[3])
        : "r"(a[0]), "r"(a[1]), "r"(a[2]), "r"(a[3]), "r"(b[0]), "r"(b[1]));
}

__device__ __forceinline__ float gelu_exact(float x) {
    return 0.5f * x * (1.0f + erff(x * 0.7071067811865476f));
}

// ---------------- fp16x2 GEMM via mma.sync, BM=128 BN=128 BK=32, 3-stage ----------------
// C = (Ah + Al) @ Bh^T  with fp32 accumulate
// EPI 0: Cf = D + bias                       (fp32 out)
// EPI 1: (Ch,Cl) = split(gelu(D + bias))     (fp16 hi/lo out)
// EPI 2: Cf = D + bias + resid               (fp32 out)
#define BKK       32
#define RSTRIDE   40                        // fp16 elements per smem row (32 + 8 pad)
#define TILE_B    (128 * RSTRIDE * 2)       // 10240 bytes per matrix tile
#define STAGE_B   (3 * TILE_B)              // Ahi, Alo, Bhi = 30720
#define NSTAGE    3
#define GEMM_SMEM (NSTAGE * STAGE_B)        // 92160

template <int EPI>
__global__ void __launch_bounds__(256, 2) gemm_mma(
    const __half* __restrict__ Ah, const __half* __restrict__ Al,
    const __half* __restrict__ Bh,
    const float* __restrict__ bias, const float* __restrict__ resid,
    float* __restrict__ Cf, __half* __restrict__ Ch, __half* __restrict__ Cl,
    int N, int K)
{
    extern __shared__ __align__(256) char smem[];
    const uint32_t sb = smem_u32(smem);

    const int tid = threadIdx.x;
    const int wid = tid >> 5;
    const int lane = tid & 31;
    const int bm = blockIdx.y * 128;
    const int bn = blockIdx.x * 128;
    const int mOff = (wid & 3) * 32;
    const int nOff = (wid >> 2) * 64;

    // per-thread ldmatrix source row/col selectors
    const int aRow = lane & 15;
    const int aCol = (lane >> 4) * 8;
    const int bRow = (lane & 7) + ((lane >> 4) << 3);
    const int bCol = ((lane >> 3) & 1) * 8;

    float acc[2][8][4];
    #pragma unroll
    for (int i = 0; i < 2; ++i)
        #pragma unroll
        for (int j = 0; j < 8; ++j)
            #pragma unroll
            for (int k = 0; k < 4; ++k) acc[i][j][k] = 0.0f;

    const int nch = K / BKK;

    // stage loader: 2 chunks of 16B per thread per matrix (Ah, Al, Bh)
    auto loadStage = [&](int s, int it) {
        const int k0 = it * BKK;
        const uint32_t st = sb + s * STAGE_B;
        #pragma unroll
        for (int i = 0; i < 2; ++i) {
            const int id = tid + i * 256;
            const int r = id >> 2, c = id & 3;
            const uint32_t so = (uint32_t)(r * (RSTRIDE * 2) + c * 16);
            const size_t goa = (size_t)(bm + r) * K + k0 + c * 8;
            const size_t gob = (size_t)(bn + r) * K + k0 + c * 8;
            cp16(st + so,              Ah + goa);
            cp16(st + TILE_B + so,     Al + goa);
            cp16(st + 2 * TILE_B + so, Bh + gob);
        }
        asm volatile("cp.async.commit_group;" ::: "memory");
    };

    loadStage(0, 0);
    loadStage(1, 1);

    for (int it = 0; it < nch; ++it) {
        if (it + 1 < nch)
            asm volatile("cp.async.wait_group 1;" ::: "memory");
        else
            asm volatile("cp.async.wait_group 0;" ::: "memory");
        __syncthreads();

        // prefetch stage it+2 (distinct buffer from the one consumed now and the pending one)
        if (it + 2 < nch) loadStage((it + 2) % NSTAGE, it + 2);

        const uint32_t st = sb + (it % NSTAGE) * STAGE_B;
        const uint32_t pAh = st, pAl = st + TILE_B, pBh = st + 2 * TILE_B;

        #pragma unroll
        for (int kk = 0; kk < 2; ++kk) {
            uint32_t ah[2][4], al[2][4], b[4][4];
            #pragma unroll
            for (int mf = 0; mf < 2; ++mf) {
                ldm_x4(ah[mf], pAh +
                    (uint32_t)(((mOff + mf * 16 + aRow) * RSTRIDE + kk * 16 + aCol) * 2));
                ldm_x4(al[mf], pAl +
                    (uint32_t)(((mOff + mf * 16 + aRow) * RSTRIDE + kk * 16 + aCol) * 2));
            }
            #pragma unroll
            for (int n2 = 0; n2 < 4; ++n2)
                ldm_x4(b[n2], pBh +
                    (uint32_t)(((nOff + n2 * 16 + bRow) * RSTRIDE + kk * 16 + bCol) * 2));
            #pragma unroll
            for (int mf = 0; mf < 2; ++mf)
                #pragma unroll
                for (int nf = 0; nf < 8; ++nf)
                    mma_f16(acc[mf][nf], ah[mf], &b[nf >> 1][(nf & 1) * 2]);
            #pragma unroll
            for (int mf = 0; mf < 2; ++mf)
                #pragma unroll
                for (int nf = 0; nf < 8; ++nf)
                    mma_f16(acc[mf][nf], al[mf], &b[nf >> 1][(nf & 1) * 2]);
        }
    }

    // ---- epilogue ----
    #pragma unroll
    for (int mf = 0; mf < 2; ++mf) {
        #pragma unroll
        for (int half_ = 0; half_ < 2; ++half_) {
            const int row = bm + mOff + mf * 16 + (lane >> 2) + half_ * 8;
            #pragma unroll
            for (int nf = 0; nf < 8; ++nf) {
                const int col = bn + nOff + nf * 8 + (lane & 3) * 2;
                float v0 = acc[mf][nf][half_ * 2 + 0] + bias[col];
                float v1 = acc[mf][nf][half_ * 2 + 1] + bias[col + 1];
                if (EPI == 1) {
                    v0 = gelu_exact(v0);
                    v1 = gelu_exact(v1);
                    __half h0 = __float2half_rn(v0);
                    __half h1 = __float2half_rn(v1);
                    __half l0 = __float2half_rn(v0 - __half2float(h0));
                    __half l1 = __float2half_rn(v1 - __half2float(h1));
                    uint32_t hp = (uint32_t)__half_as_ushort(h0) |
                                  ((uint32_t)__half_as_ushort(h1) << 16);
                    uint32_t lp = (uint32_t)__half_as_ushort(l0) |
                                  ((uint32_t)__half_as_ushort(l1) << 16);
                    *reinterpret_cast<uint32_t*>(Ch + (size_t)row * N + col) = hp;
                    *reinterpret_cast<uint32_t*>(Cl + (size_t)row * N + col) = lp;
                } else {
                    if (EPI == 2) {
                        const float* rp = resid + (size_t)row * N + col;
                        v0 += rp[0];
                        v1 += rp[1];
                    }
                    *reinterpret_cast<float2*>(Cf + (size_t)row * N + col) = make_float2(v0, v1);
                }
            }
        }
    }
}

// ---------------- fp32 -> fp16 hi/lo split (elementwise) ----------------
__global__ void __launch_bounds__(256) split_kernel(
    const float* __restrict__ x, __half* __restrict__ h, __half* __restrict__ l, int n4)
{
    int i = blockIdx.x * 256 + threadIdx.x;
    if (i >= n4) return;
    float4 v = reinterpret_cast<const float4*>(x)[i];
    __half h0 = __float2half_rn(v.x), h1 = __float2half_rn(v.y);
    __half h2 = __float2half_rn(v.z), h3 = __float2half_rn(v.w);
    __half l0 = __float2half_rn(v.x - __half2float(h0));
    __half l1 = __float2half_rn(v.y - __half2float(h1));
    __half l2 = __float2half_rn(v.z - __half2float(h2));
    __half l3 = __float2half_rn(v.w - __half2float(h3));
    __half hb[4] = {h0, h1, h2, h3}, lb[4] = {l0, l1, l2, l3};
    reinterpret_cast<uint2*>(h)[i] = *reinterpret_cast<const uint2*>(hb);
    reinterpret_cast<uint2*>(l)[i] = *reinterpret_cast<const uint2*>(lb);
}

// ---------------- W[K][N] fp32 -> Wt[N][K] fp16 ----------------
__global__ void __launch_bounds__(256) transpose_h(
    const float* __restrict__ W, __half* __restrict__ Th, int K, int N)
{
    __shared__ float s[32][33];
    const int n0 = blockIdx.x * 32, k0 = blockIdx.y * 32;
    const int c = threadIdx.x & 31, r0 = threadIdx.x >> 5;
    #pragma unroll
    for (int r = r0; r < 32; r += 8)
        s[r][c] = W[(size_t)(k0 + r) * N + n0 + c];
    __syncthreads();
    #pragma unroll
    for (int r = r0; r < 32; r += 8)
        Th[(size_t)(n0 + r) * K + k0 + c] = __float2half_rn(s[c][r]);
}

// ---------------- block reduce helpers ----------------
__device__ __forceinline__ float blockReduceMax(float v) {
    __shared__ float sm[8];
    #pragma unroll
    for (int o = 16; o > 0; o >>= 1) v = fmaxf(v, __shfl_xor_sync(0xffffffffu, v, o));
    int wid = threadIdx.x >> 5, nw = blockDim.x >> 5;
    if ((threadIdx.x & 31) == 0) sm[wid] = v;
    __syncthreads();
    float r = -1e30f;
    for (int i = 0; i < nw; ++i) r = fmaxf(r, sm[i]);
    __syncthreads();
    return r;
}
__device__ __forceinline__ float blockReduceSum(float v) {
    __shared__ float sm[8];
    #pragma unroll
    for (int o = 16; o > 0; o >>= 1) v += __shfl_xor_sync(0xffffffffu, v, o);
    int wid = threadIdx.x >> 5, nw = blockDim.x >> 5;
    if ((threadIdx.x & 31) == 0) sm[wid] = v;
    __syncthreads();
    float r = 0.0f;
    for (int i = 0; i < nw; ++i) r += sm[i];
    __syncthreads();
    return r;
}
__device__ __forceinline__ void blockReduceSum2(float& a, float& b) {
    __shared__ float sa[8], sb[8];
    #pragma unroll
    for (int o = 16; o > 0; o >>= 1) {
        a += __shfl_xor_sync(0xffffffffu, a, o);
        b += __shfl_xor_sync(0xffffffffu, b, o);
    }
    int wid = threadIdx.x >> 5, nw = blockDim.x >> 5;
    if ((threadIdx.x & 31) == 0) { sa[wid] = a; sb[wid] = b; }
    __syncthreads();
    float ra = 0.0f, rb = 0.0f;
    for (int i = 0; i < nw; ++i) { ra += sa[i]; rb += sb[i]; }
    __syncthreads();
    a = ra; b = rb;
}

// ---------------- aff[b,h,c,p] = (1/8) * sum_d cores[h,c,d] * q[b,p,h*64+d] ----------------
__global__ void __launch_bounds__(256) aff_kernel(
    const float* __restrict__ q, const float* __restrict__ cores, float* __restrict__ aff)
{
    __shared__ float cs[64][65];
    __shared__ float qs[64][65];
    const int b = blockIdx.z, h = blockIdx.y, p0 = blockIdx.x * 64;
    const int tid = threadIdx.x;
    const int lr = tid >> 2;
    const int lc = (tid & 3) * 16;
    #pragma unroll
    for (int u = 0; u < 4; ++u) {
        float4 cv = *reinterpret_cast<const float4*>(cores + (size_t)(h * CC + lr) * HD_ + lc + u * 4);
        cs[lr][lc + u * 4 + 0] = cv.x; cs[lr][lc + u * 4 + 1] = cv.y;
        cs[lr][lc + u * 4 + 2] = cv.z; cs[lr][lc + u * 4 + 3] = cv.w;
        float4 qv = *reinterpret_cast<const float4*>(q + (size_t)(b * PP + p0 + lr) * DD + h * HD_ + lc + u * 4);
        qs[lr][lc + u * 4 + 0] = qv.x; qs[lr][lc + u * 4 + 1] = qv.y;
        qs[lr][lc + u * 4 + 2] = qv.z; qs[lr][lc + u * 4 + 3] = qv.w;
    }
    __syncthreads();
    const int c0 = (tid & 15) * 4;
    const int pq = (tid >> 4) * 4;
    float acc[4][4];
    #pragma unroll
    for (int i = 0; i < 4; ++i)
        #pragma unroll
        for (int j = 0; j < 4; ++j) acc[i][j] = 0.0f;
    #pragma unroll 8
    for (int k = 0; k < 64; ++k) {
        float cr[4], pr[4];
        #pragma unroll
        for (int i = 0; i < 4; ++i) cr[i] = cs[c0 + i][k];
        #pragma unroll
        for (int j = 0; j < 4; ++j) pr[j] = qs[pq + j][k];
        #pragma unroll
        for (int i = 0; i < 4; ++i)
            #pragma unroll
            for (int j = 0; j < 4; ++j) acc[i][j] = fmaf(cr[i], pr[j], acc[i][j]);
    }
    const size_t base = ((size_t)(b * HH + h) * CC) * PP;
    #pragma unroll
    for (int i = 0; i < 4; ++i) {
        float4 o = make_float4(acc[i][0] * 0.125f, acc[i][1] * 0.125f,
                               acc[i][2] * 0.125f, acc[i][3] * 0.125f);
        *reinterpret_cast<float4*>(aff + base + (size_t)(c0 + i) * PP + p0 + pq) = o;
    }
}

// ---------------- softmax over cores ----------------
__global__ void __launch_bounds__(256) p2c_softmax(
    const float* __restrict__ aff, float* __restrict__ p2c)
{
    const size_t base = (size_t)blockIdx.x * CC * PP;
    const float* in = aff + base;
    float* out = p2c + base;
    for (int p = threadIdx.x; p < PP; p += 256) {
        float m = -1e30f, s = 0.0f;
        #pragma unroll
        for (int c = 0; c < CC; ++c) {
            float x = in[(size_t)c * PP + p];
            float nm = fmaxf(m, x);
            s = s * __expf(m - nm) + __expf(x - nm);
            m = nm;
        }
        const float inv = 1.0f / s;
        #pragma unroll
        for (int c = 0; c < CC; ++c)
            out[(size_t)c * PP + p] = __expf(in[(size_t)c * PP + p] - m) * inv;
    }
}

// ---------------- softmax over patches (in-place) ----------------
__global__ void __launch_bounds__(256) c2p_softmax(float* __restrict__ a)
{
    float* row = a + (size_t)blockIdx.x * PP;
    const int t = threadIdx.x;
    float x[8];
    *reinterpret_cast<float4*>(x)     = *reinterpret_cast<const float4*>(row + t * 8);
    *reinterpret_cast<float4*>(x + 4) = *reinterpret_cast<const float4*>(row + t * 8 + 4);
    float m = -1e30f;
    #pragma unroll
    for (int i = 0; i < 8; ++i) m = fmaxf(m, x[i]);
    m = blockReduceMax(m);
    float s = 0.0f;
    #pragma unroll
    for (int i = 0; i < 8; ++i) { x[i] = __expf(x[i] - m); s += x[i]; }
    s = blockReduceSum(s);
    const float inv = 1.0f / s;
    #pragma unroll
    for (int i = 0; i < 8; ++i) x[i] *= inv;
    *reinterpret_cast<float4*>(row + t * 8)     = *reinterpret_cast<float4*>(x);
    *reinterpret_cast<float4*>(row + t * 8 + 4) = *reinterpret_cast<float4*>(x + 4);
}

// ---------------- v_core ----------------
__global__ void __launch_bounds__(256) vcore_kernel(
    const float* __restrict__ input, const float* __restrict__ c2p, float* __restrict__ vcore)
{
    __shared__ float asT[64][68];
    __shared__ float vs[64][68];
    const int h = blockIdx.x, b = blockIdx.y;
    const int bh = b * HH + h;
    const float* abase = c2p + (size_t)bh * CC * PP;
    const int tid = threadIdx.x;
    const int lr = tid >> 2;
    const int lc = (tid & 3) * 16;
    const int c0 = (tid & 15) * 4;
    const int d0 = (tid >> 4) * 4;
    float acc[4][4];
    #pragma unroll
    for (int i = 0; i < 4; ++i)
        #pragma unroll
        for (int j = 0; j < 4; ++j) acc[i][j] = 0.0f;

    for (int pt = 0; pt < PP; pt += 64) {
        #pragma unroll
        for (int u = 0; u < 4; ++u) {
            float4 av = *reinterpret_cast<const float4*>(abase + (size_t)lr * PP + pt + lc + u * 4);
            asT[lc + u * 4 + 0][lr] = av.x; asT[lc + u * 4 + 1][lr] = av.y;
            asT[lc + u * 4 + 2][lr] = av.z; asT[lc + u * 4 + 3][lr] = av.w;
            float4 vv = *reinterpret_cast<const float4*>(input + (size_t)(b * PP + pt + lr) * DD + h * HD_ + lc + u * 4);
            *reinterpret_cast<float4*>(&vs[lr][lc + u * 4]) = vv;
        }
        __syncthreads();
        #pragma unroll 16
        for (int k = 0; k < 64; ++k) {
            float4 ar = *reinterpret_cast<const float4*>(&asT[k][c0]);
            float4 vr = *reinterpret_cast<const float4*>(&vs[k][d0]);
            float arr[4] = {ar.x, ar.y, ar.z, ar.w};
            float vrr[4] = {vr.x, vr.y, vr.z, vr.w};
            #pragma unroll
            for (int i = 0; i < 4; ++i)
                #pragma unroll
                for (int j = 0; j < 4; ++j) acc[i][j] = fmaf(arr[i], vrr[j], acc[i][j]);
        }
        __syncthreads();
    }
    #pragma unroll
    for (int i = 0; i < 4; ++i) {
        float4 o = make_float4(acc[i][0], acc[i][1], acc[i][2], acc[i][3]);
        *reinterpret_cast<float4*>(vcore + (size_t)(bh * CC + c0 + i) * HD_ + d0) = o;
    }
}

// ---------------- v_patch + ffn_in concat (writes fp16 hi/lo) ----------------
__device__ __forceinline__ void split_store4(__half* ph, __half* pl, float4 v) {
    __half h0 = __float2half_rn(v.x), h1 = __float2half_rn(v.y);
    __half h2 = __float2half_rn(v.z), h3 = __float2half_rn(v.w);
    __half l0 = __float2half_rn(v.x - __half2float(h0));
    __half l1 = __float2half_rn(v.y - __half2float(h1));
    __half l2 = __float2half_rn(v.z - __half2float(h2));
    __half l3 = __float2half_rn(v.w - __half2float(h3));
    __half hb[4] = {h0, h1, h2, h3}, lb[4] = {l0, l1, l2, l3};
    *reinterpret_cast<uint2*>(ph) = *reinterpret_cast<const uint2*>(hb);
    *reinterpret_cast<uint2*>(pl) = *reinterpret_cast<const uint2*>(lb);
}

__global__ void __launch_bounds__(256) vpatch_ffn_kernel(
    const float* __restrict__ input, const float* __restrict__ vcore,
    const float* __restrict__ p2c,
    __half* __restrict__ fh, __half* __restrict__ fl)
{
    __shared__ float vc[64][65];
    __shared__ float ap[64][65];
    const int b = blockIdx.z, h = blockIdx.y, p0 = blockIdx.x * 64;
    const int bh = b * HH + h;
    const int tid = threadIdx.x;
    const int lr = tid >> 2;
    const int lc = (tid & 3) * 16;
    #pragma unroll
    for (int u = 0; u < 4; ++u) {
        float4 cv = *reinterpret_cast<const float4*>(vcore + (size_t)(bh * CC + lr) * HD_ + lc + u * 4);
        vc[lr][lc + u * 4 + 0] = cv.x; vc[lr][lc + u * 4 + 1] = cv.y;
        vc[lr][lc + u * 4 + 2] = cv.z; vc[lr][lc + u * 4 + 3] = cv.w;
        float4 av = *reinterpret_cast<const float4*>(p2c + ((size_t)(bh * CC + lr)) * PP + p0 + lc + u * 4);
        ap[lr][lc + u * 4 + 0] = av.x; ap[lr][lc + u * 4 + 1] = av.y;
        ap[lr][lc + u * 4 + 2] = av.z; ap[lr][lc + u * 4 + 3] = av.w;
    }
    __syncthreads();
    const int pq = (tid >> 4) * 4;
    const int d0 = (tid & 15) * 4;
    float acc[4][4];
    #pragma unroll
    for (int i = 0; i < 4; ++i)
        #pragma unroll
        for (int j = 0; j < 4; ++j) acc[i][j] = 0.0f;
    #pragma unroll 8
    for (int k = 0; k < 64; ++k) {
        float apr[4], vcr[4];
        #pragma unroll
        for (int i = 0; i < 4; ++i) apr[i] = ap[k][pq + i];
        #pragma unroll
        for (int j = 0; j < 4; ++j) vcr[j] = vc[k][d0 + j];
        #pragma unroll
        for (int i = 0; i < 4; ++i)
            #pragma unroll
            for (int j = 0; j < 4; ++j) acc[i][j] = fmaf(apr[i], vcr[j], acc[i][j]);
    }
    #pragma unroll
    for (int i = 0; i < 4; ++i) {
        const int gp = b * PP + p0 + pq + i;
        float4 inp = *reinterpret_cast<const float4*>(input + (size_t)gp * DD + h * HD_ + d0);
        float4 vp = make_float4(acc[i][0], acc[i][1], acc[i][2], acc[i][3]);
        float4 diff = make_float4(inp.x - vp.x, inp.y - vp.y, inp.z - vp.z, inp.w - vp.w);
        const size_t fo = (size_t)gp * FFNIN + h * HD_ + d0;
        split_store4(fh + fo, fl + fo, diff);
        split_store4(fh + fo + DD, fl + fo + DD, vp);
    }
}

// ---------------- LayerNorm ----------------
__global__ void __launch_bounds__(128) ln_kernel(
    const float* __restrict__ x, const float* __restrict__ gamma,
    const float* __restrict__ beta, float* __restrict__ out)
{
    const float* row = x + (size_t)blockIdx.x * DD;
    const int t = threadIdx.x;
    float4 v = *reinterpret_cast<const float4*>(row + t * 4);
    float s = v.x + v.y + v.z + v.w;
    float sq = v.x * v.x + v.y * v.y + v.z * v.z + v.w * v.w;
    blockReduceSum2(s, sq);
    const float mu = s * (1.0f / DD);
    const float var = sq * (1.0f / DD) - mu * mu;
    const float rstd = rsqrtf(var + 1e-5f);
    float4 g = *reinterpret_cast<const float4*>(gamma + t * 4);
    float4 bt = *reinterpret_cast<const float4*>(beta + t * 4);
    float4 o;
    o.x = (v.x - mu) * rstd * g.x + bt.x;
    o.y = (v.y - mu) * rstd * g.y + bt.y;
    o.z = (v.z - mu) * rstd * g.z + bt.z;
    o.w = (v.w - mu) * rstd * g.w + bt.w;
    *reinterpret_cast<float4*>(out + (size_t)blockIdx.x * DD + t * 4) = o;
}

// ---------------- launch ----------------
extern "C" void kernel_launch(void* const* d_in, const int* in_sizes, int n_in,
                              void* d_out, int out_size)
{
    (void)in_sizes; (void)n_in; (void)out_size;
    const float* input = (const float*)d_in[0];
    const float* cores = (const float*)d_in[1];
    const float* Wv    = (const float*)d_in[2];
    const float* bv    = (const float*)d_in[3];
    const float* W1    = (const float*)d_in[4];
    const float* b1    = (const float*)d_in[5];
    const float* W2    = (const float*)d_in[6];
    const float* b2    = (const float*)d_in[7];
    const float* gamma = (const float*)d_in[8];
    const float* beta  = (const float*)d_in[9];
    float* out = (float*)d_out;

    float *q, *aff, *p2c, *vcore, *outp;
    __half *in_hi, *in_lo, *ffn_hi, *ffn_lo, *hid_hi, *hid_lo;
    __half *wvT, *w1T, *w2T;
    cudaGetSymbolAddress((void**)&q, g_q);
    cudaGetSymbolAddress((void**)&aff, g_aff);
    cudaGetSymbolAddress((void**)&p2c, g_p2c);
    cudaGetSymbolAddress((void**)&vcore, g_vcore);
    cudaGetSymbolAddress((void**)&outp, g_outp);
    cudaGetSymbolAddress((void**)&in_hi, g_in_hi);
    cudaGetSymbolAddress((void**)&in_lo, g_in_lo);
    cudaGetSymbolAddress((void**)&ffn_hi, g_ffn_hi);
    cudaGetSymbolAddress((void**)&ffn_lo, g_ffn_lo);
    cudaGetSymbolAddress((void**)&hid_hi, g_hid_hi);
    cudaGetSymbolAddress((void**)&hid_lo, g_hid_lo);
    cudaGetSymbolAddress((void**)&wvT, g_wvT);
    cudaGetSymbolAddress((void**)&w1T, g_w1T);
    cudaGetSymbolAddress((void**)&w2T, g_w2T);

    cudaFuncSetAttribute(gemm_mma<0>, cudaFuncAttributeMaxDynamicSharedMemorySize, GEMM_SMEM);
    cudaFuncSetAttribute(gemm_mma<1>, cudaFuncAttributeMaxDynamicSharedMemorySize, GEMM_SMEM);
    cudaFuncSetAttribute(gemm_mma<2>, cudaFuncAttributeMaxDynamicSharedMemorySize, GEMM_SMEM);

    // prep: splits + weight transposes
    split_kernel<<<(MM * DD / 4 + 255) / 256, 256>>>(input, in_hi, in_lo, MM * DD / 4);
    transpose_h<<<dim3(DD / 32, DD / 32), 256>>>(Wv, wvT, DD, DD);
    transpose_h<<<dim3(FFNHID / 32, FFNIN / 32), 256>>>(W1, w1T, FFNIN, FFNHID);
    transpose_h<<<dim3(DD / 32, FFNHID / 32), 256>>>(W2, w2T, FFNHID, DD);

    // 1. q = input @ Wv + bv
    gemm_mma<0><<<dim3(DD / 128, MM / 128), 256, GEMM_SMEM>>>(
        in_hi, in_lo, wvT, bv, nullptr, q, nullptr, nullptr, DD, DD);
    // 2-5. affinity + dual softmax + aggregate + redistribute
    aff_kernel<<<dim3(PP / 64, HH, BB), 256>>>(q, cores, aff);
    p2c_softmax<<<BB * HH, 256>>>(aff, p2c);
    c2p_softmax<<<BB * HH * CC, 256>>>(aff);
    vcore_kernel<<<dim3(HH, BB), 256>>>(input, aff, vcore);
    vpatch_ffn_kernel<<<dim3(PP / 64, HH, BB), 256>>>(input, vcore, p2c, ffn_hi, ffn_lo);
    // 6. hid = gelu(ffn @ W1 + b1)   (fp16 hi/lo out)
    gemm_mma<1><<<dim3(FFNHID / 128, MM / 128), 256, GEMM_SMEM>>>(
        ffn_hi, ffn_lo, w1T, b1, nullptr, nullptr, hid_hi, hid_lo, FFNHID, FFNIN);
    // 7. outp = input + hid @ W2 + b2
    gemm_mma<2><<<dim3(DD / 128, MM / 128), 256, GEMM_SMEM>>>(
        hid_hi, hid_lo, w2T, b2, input, outp, nullptr, nullptr, DD, FFNHID);
    // 8. LayerNorm
    ln_kernel<<<MM, 128>>>(outp, gamma, beta, out);
}

// round 6
// speedup vs baseline: 5.4969x; 1.5364x over previous
#include <cuda_runtime.h>
#include <cuda_fp16.h>
#include <math.h>
#include <stdint.h>

// ---------------- problem constants ----------------
#define BB      16
#define PP      2048
#define DD      512
#define HH      8
#define CC      64
#define HD_     64
#define MM      (BB * PP)        // 32768
#define FFNIN   1024
#define FFNHID  4096

// ---------------- scratch (device globals; allocation-free) ----------------
__device__ __align__(256) float g_q[MM * DD];
__device__ __align__(256) float g_aff[BB * HH * CC * PP];
__device__ __align__(256) float g_p2c[BB * HH * CC * PP];
__device__ __align__(256) float g_vcore[BB * HH * CC * HD_];
__device__ __align__(256) float g_outp[MM * DD];

__device__ __align__(256) __half g_in_h[MM * DD];
__device__ __align__(256) __half g_ffn_h[MM * FFNIN];
__device__ __align__(256) __half g_hid_h[(size_t)MM * FFNHID];
// weights transposed to [N][K] fp16
__device__ __align__(256) __half g_wvT[DD * DD];
__device__ __align__(256) __half g_w1T[FFNHID * FFNIN];
__device__ __align__(256) __half g_w2T[DD * FFNHID];

// ---------------- PTX helpers (sm_80-era instructions only) ----------------
__device__ __forceinline__ uint32_t smem_u32(const void* p) {
    uint32_t a;
    asm("{ .reg .u64 t; cvta.to.shared.u64 t, %1; cvt.u32.u64 %0, t; }" : "=r"(a) : "l"(p));
    return a;
}
__device__ __forceinline__ void cp16(uint32_t s, const void* g) {
    asm volatile("cp.async.cg.shared.global [%0], [%1], 16;" :: "r"(s), "l"(g));
}
__device__ __forceinline__ void ldm_x4(uint32_t* r, uint32_t addr) {
    asm volatile("ldmatrix.sync.aligned.m8n8.x4.shared.b16 {%0,%1,%2,%3}, [%4];"
                 : "=r"(r[0]), "=r"(r[1]), "=r"(r[2]), "=r"(r[3]) : "r"(addr));
}
__device__ __forceinline__ void mma_f16(float* d, const uint32_t* a, const uint32_t* b) {
    asm volatile(
        "mma.sync.aligned.m16n8k16.row.col.f32.f16.f16.f32 "
        "{%0,%1,%2,%3}, {%4,%5,%6,%7}, {%8,%9}, {%0,%1,%2,%3};"
        : "+f"(d[0]), "+f"(d[1]), "+f"(d[2]), "+f"(d[3])
        : "r"(a[0]), "r"(a[1]), "r"(a[2]), "r"(a[3]), "r"(b[0]), "r"(b[1]));
}

__device__ __forceinline__ float gelu_exact(float x) {
    return 0.5f * x * (1.0f + erff(x * 0.7071067811865476f));
}

// ---------------- fp16 GEMM via mma.sync, BM=128 BN=128 BK=32, 3-stage ----------------
// C = Ah @ Bh^T  with fp32 accumulate
// EPI 0: Cf = D + bias                       (fp32 out)
// EPI 1: Ch = half(gelu(D + bias))           (fp16 out)
// EPI 2: Cf = D + bias + resid               (fp32 out)
#define BKK       32
#define RSTRIDE   40                        // fp16 elements per smem row (32 + 8 pad)
#define TILE_B    (128 * RSTRIDE * 2)       // 10240 bytes per matrix tile
#define STAGE_B   (2 * TILE_B)              // Ah, Bh = 20480
#define NSTAGE    3
#define GEMM_SMEM (NSTAGE * STAGE_B)        // 61440

template <int EPI>
__global__ void __launch_bounds__(256, 2) gemm_mma(
    const __half* __restrict__ Ah, const __half* __restrict__ Bh,
    const float* __restrict__ bias, const float* __restrict__ resid,
    float* __restrict__ Cf, __half* __restrict__ Ch,
    int N, int K)
{
    extern __shared__ __align__(256) char smem[];
    const uint32_t sb = smem_u32(smem);

    const int tid = threadIdx.x;
    const int wid = tid >> 5;
    const int lane = tid & 31;
    const int bm = blockIdx.y * 128;
    const int bn = blockIdx.x * 128;
    const int mOff = (wid & 3) * 32;
    const int nOff = (wid >> 2) * 64;

    // per-thread ldmatrix source row/col selectors
    const int aRow = lane & 15;
    const int aCol = (lane >> 4) * 8;
    const int bRow = (lane & 7) + ((lane >> 4) << 3);
    const int bCol = ((lane >> 3) & 1) * 8;

    float acc[2][8][4];
    #pragma unroll
    for (int i = 0; i < 2; ++i)
        #pragma unroll
        for (int j = 0; j < 8; ++j)
            #pragma unroll
            for (int k = 0; k < 4; ++k) acc[i][j][k] = 0.0f;

    const int nch = K / BKK;

    // stage loader: 2 chunks of 16B per thread per matrix (Ah, Bh)
    auto loadStage = [&](int s, int it) {
        const int k0 = it * BKK;
        const uint32_t st = sb + s * STAGE_B;
        #pragma unroll
        for (int i = 0; i < 2; ++i) {
            const int id = tid + i * 256;
            const int r = id >> 2, c = id & 3;
            const uint32_t so = (uint32_t)(r * (RSTRIDE * 2) + c * 16);
            cp16(st + so,          Ah + (size_t)(bm + r) * K + k0 + c * 8);
            cp16(st + TILE_B + so, Bh + (size_t)(bn + r) * K + k0 + c * 8);
        }
        asm volatile("cp.async.commit_group;" ::: "memory");
    };

    loadStage(0, 0);
    loadStage(1, 1);

    for (int it = 0; it < nch; ++it) {
        if (it + 1 < nch)
            asm volatile("cp.async.wait_group 1;" ::: "memory");
        else
            asm volatile("cp.async.wait_group 0;" ::: "memory");
        __syncthreads();

        // prefetch stage it+2 (distinct buffer from the one consumed now and the pending one)
        if (it + 2 < nch) loadStage((it + 2) % NSTAGE, it + 2);

        const uint32_t st = sb + (it % NSTAGE) * STAGE_B;
        const uint32_t pAh = st, pBh = st + TILE_B;

        #pragma unroll
        for (int kk = 0; kk < 2; ++kk) {
            uint32_t ah[2][4], b[4][4];
            #pragma unroll
            for (int mf = 0; mf < 2; ++mf)
                ldm_x4(ah[mf], pAh +
                    (uint32_t)(((mOff + mf * 16 + aRow) * RSTRIDE + kk * 16 + aCol) * 2));
            #pragma unroll
            for (int n2 = 0; n2 < 4; ++n2)
                ldm_x4(b[n2], pBh +
                    (uint32_t)(((nOff + n2 * 16 + bRow) * RSTRIDE + kk * 16 + bCol) * 2));
            #pragma unroll
            for (int mf = 0; mf < 2; ++mf)
                #pragma unroll
                for (int nf = 0; nf < 8; ++nf)
                    mma_f16(acc[mf][nf], ah[mf], &b[nf >> 1][(nf & 1) * 2]);
        }
    }

    // ---- epilogue ----
    #pragma unroll
    for (int mf = 0; mf < 2; ++mf) {
        #pragma unroll
        for (int half_ = 0; half_ < 2; ++half_) {
            const int row = bm + mOff + mf * 16 + (lane >> 2) + half_ * 8;
            #pragma unroll
            for (int nf = 0; nf < 8; ++nf) {
                const int col = bn + nOff + nf * 8 + (lane & 3) * 2;
                float v0 = acc[mf][nf][half_ * 2 + 0] + bias[col];
                float v1 = acc[mf][nf][half_ * 2 + 1] + bias[col + 1];
                if (EPI == 1) {
                    v0 = gelu_exact(v0);
                    v1 = gelu_exact(v1);
                    __half h0 = __float2half_rn(v0);
                    __half h1 = __float2half_rn(v1);
                    uint32_t hp = (uint32_t)__half_as_ushort(h0) |
                                  ((uint32_t)__half_as_ushort(h1) << 16);
                    *reinterpret_cast<uint32_t*>(Ch + (size_t)row * N + col) = hp;
                } else {
                    if (EPI == 2) {
                        const float* rp = resid + (size_t)row * N + col;
                        v0 += rp[0];
                        v1 += rp[1];
                    }
                    *reinterpret_cast<float2*>(Cf + (size_t)row * N + col) = make_float2(v0, v1);
                }
            }
        }
    }
}

// ---------------- fp32 -> fp16 convert (elementwise) ----------------
__global__ void __launch_bounds__(256) cvt_kernel(
    const float* __restrict__ x, __half* __restrict__ h, int n4)
{
    int i = blockIdx.x * 256 + threadIdx.x;
    if (i >= n4) return;
    float4 v = reinterpret_cast<const float4*>(x)[i];
    __half hb[4] = {__float2half_rn(v.x), __float2half_rn(v.y),
                    __float2half_rn(v.z), __float2half_rn(v.w)};
    reinterpret_cast<uint2*>(h)[i] = *reinterpret_cast<const uint2*>(hb);
}

// ---------------- W[K][N] fp32 -> Wt[N][K] fp16 ----------------
__global__ void __launch_bounds__(256) transpose_h(
    const float* __restrict__ W, __half* __restrict__ Th, int K, int N)
{
    __shared__ float s[32][33];
    const int n0 = blockIdx.x * 32, k0 = blockIdx.y * 32;
    const int c = threadIdx.x & 31, r0 = threadIdx.x >> 5;
    #pragma unroll
    for (int r = r0; r < 32; r += 8)
        s[r][c] = W[(size_t)(k0 + r) * N + n0 + c];
    __syncthreads();
    #pragma unroll
    for (int r = r0; r < 32; r += 8)
        Th[(size_t)(n0 + r) * K + k0 + c] = __float2half_rn(s[c][r]);
}

// ---------------- block reduce helpers ----------------
__device__ __forceinline__ float blockReduceMax(float v) {
    __shared__ float sm[8];
    #pragma unroll
    for (int o = 16; o > 0; o >>= 1) v = fmaxf(v, __shfl_xor_sync(0xffffffffu, v, o));
    int wid = threadIdx.x >> 5, nw = blockDim.x >> 5;
    if ((threadIdx.x & 31) == 0) sm[wid] = v;
    __syncthreads();
    float r = -1e30f;
    for (int i = 0; i < nw; ++i) r = fmaxf(r, sm[i]);
    __syncthreads();
    return r;
}
__device__ __forceinline__ float blockReduceSum(float v) {
    __shared__ float sm[8];
    #pragma unroll
    for (int o = 16; o > 0; o >>= 1) v += __shfl_xor_sync(0xffffffffu, v, o);
    int wid = threadIdx.x >> 5, nw = blockDim.x >> 5;
    if ((threadIdx.x & 31) == 0) sm[wid] = v;
    __syncthreads();
    float r = 0.0f;
    for (int i = 0; i < nw; ++i) r += sm[i];
    __syncthreads();
    return r;
}
__device__ __forceinline__ void blockReduceSum2(float& a, float& b) {
    __shared__ float sa[8], sb[8];
    #pragma unroll
    for (int o = 16; o > 0; o >>= 1) {
        a += __shfl_xor_sync(0xffffffffu, a, o);
        b += __shfl_xor_sync(0xffffffffu, b, o);
    }
    int wid = threadIdx.x >> 5, nw = blockDim.x >> 5;
    if ((threadIdx.x & 31) == 0) { sa[wid] = a; sb[wid] = b; }
    __syncthreads();
    float ra = 0.0f, rb = 0.0f;
    for (int i = 0; i < nw; ++i) { ra += sa[i]; rb += sb[i]; }
    __syncthreads();
    a = ra; b = rb;
}

// ---------------- aff[b,h,c,p] = (1/8) * sum_d cores[h,c,d] * q[b,p,h*64+d] ----------------
__global__ void __launch_bounds__(256) aff_kernel(
    const float* __restrict__ q, const float* __restrict__ cores, float* __restrict__ aff)
{
    __shared__ float cs[64][65];
    __shared__ float qs[64][65];
    const int b = blockIdx.z, h = blockIdx.y, p0 = blockIdx.x * 64;
    const int tid = threadIdx.x;
    const int lr = tid >> 2;
    const int lc = (tid & 3) * 16;
    #pragma unroll
    for (int u = 0; u < 4; ++u) {
        float4 cv = *reinterpret_cast<const float4*>(cores + (size_t)(h * CC + lr) * HD_ + lc + u * 4);
        cs[lr][lc + u * 4 + 0] = cv.x; cs[lr][lc + u * 4 + 1] = cv.y;
        cs[lr][lc + u * 4 + 2] = cv.z; cs[lr][lc + u * 4 + 3] = cv.w;
        float4 qv = *reinterpret_cast<const float4*>(q + (size_t)(b * PP + p0 + lr) * DD + h * HD_ + lc + u * 4);
        qs[lr][lc + u * 4 + 0] = qv.x; qs[lr][lc + u * 4 + 1] = qv.y;
        qs[lr][lc + u * 4 + 2] = qv.z; qs[lr][lc + u * 4 + 3] = qv.w;
    }
    __syncthreads();
    const int c0 = (tid & 15) * 4;
    const int pq = (tid >> 4) * 4;
    float acc[4][4];
    #pragma unroll
    for (int i = 0; i < 4; ++i)
        #pragma unroll
        for (int j = 0; j < 4; ++j) acc[i][j] = 0.0f;
    #pragma unroll 8
    for (int k = 0; k < 64; ++k) {
        float cr[4], pr[4];
        #pragma unroll
        for (int i = 0; i < 4; ++i) cr[i] = cs[c0 + i][k];
        #pragma unroll
        for (int j = 0; j < 4; ++j) pr[j] = qs[pq + j][k];
        #pragma unroll
        for (int i = 0; i < 4; ++i)
            #pragma unroll
            for (int j = 0; j < 4; ++j) acc[i][j] = fmaf(cr[i], pr[j], acc[i][j]);
    }
    const size_t base = ((size_t)(b * HH + h) * CC) * PP;
    #pragma unroll
    for (int i = 0; i < 4; ++i) {
        float4 o = make_float4(acc[i][0] * 0.125f, acc[i][1] * 0.125f,
                               acc[i][2] * 0.125f, acc[i][3] * 0.125f);
        *reinterpret_cast<float4*>(aff + base + (size_t)(c0 + i) * PP + p0 + pq) = o;
    }
}

// ---------------- softmax over cores ----------------
__global__ void __launch_bounds__(256) p2c_softmax(
    const float* __restrict__ aff, float* __restrict__ p2c)
{
    const size_t base = (size_t)blockIdx.x * CC * PP;
    const float* in = aff + base;
    float* out = p2c + base;
    for (int p = threadIdx.x; p < PP; p += 256) {
        float m = -1e30f, s = 0.0f;
        #pragma unroll
        for (int c = 0; c < CC; ++c) {
            float x = in[(size_t)c * PP + p];
            float nm = fmaxf(m, x);
            s = s * __expf(m - nm) + __expf(x - nm);
            m = nm;
        }
        const float inv = 1.0f / s;
        #pragma unroll
        for (int c = 0; c < CC; ++c)
            out[(size_t)c * PP + p] = __expf(in[(size_t)c * PP + p] - m) * inv;
    }
}

// ---------------- softmax over patches (in-place) ----------------
__global__ void __launch_bounds__(256) c2p_softmax(float* __restrict__ a)
{
    float* row = a + (size_t)blockIdx.x * PP;
    const int t = threadIdx.x;
    float x[8];
    *reinterpret_cast<float4*>(x)     = *reinterpret_cast<const float4*>(row + t * 8);
    *reinterpret_cast<float4*>(x + 4) = *reinterpret_cast<const float4*>(row + t * 8 + 4);
    float m = -1e30f;
    #pragma unroll
    for (int i = 0; i < 8; ++i) m = fmaxf(m, x[i]);
    m = blockReduceMax(m);
    float s = 0.0f;
    #pragma unroll
    for (int i = 0; i < 8; ++i) { x[i] = __expf(x[i] - m); s += x[i]; }
    s = blockReduceSum(s);
    const float inv = 1.0f / s;
    #pragma unroll
    for (int i = 0; i < 8; ++i) x[i] *= inv;
    *reinterpret_cast<float4*>(row + t * 8)     = *reinterpret_cast<float4*>(x);
    *reinterpret_cast<float4*>(row + t * 8 + 4) = *reinterpret_cast<float4*>(x + 4);
}

// ---------------- v_core ----------------
__global__ void __launch_bounds__(256) vcore_kernel(
    const float* __restrict__ input, const float* __restrict__ c2p, float* __restrict__ vcore)
{
    __shared__ float asT[64][68];
    __shared__ float vs[64][68];
    const int h = blockIdx.x, b = blockIdx.y;
    const int bh = b * HH + h;
    const float* abase = c2p + (size_t)bh * CC * PP;
    const int tid = threadIdx.x;
    const int lr = tid >> 2;
    const int lc = (tid & 3) * 16;
    const int c0 = (tid & 15) * 4;
    const int d0 = (tid >> 4) * 4;
    float acc[4][4];
    #pragma unroll
    for (int i = 0; i < 4; ++i)
        #pragma unroll
        for (int j = 0; j < 4; ++j) acc[i][j] = 0.0f;

    for (int pt = 0; pt < PP; pt += 64) {
        #pragma unroll
        for (int u = 0; u < 4; ++u) {
            float4 av = *reinterpret_cast<const float4*>(abase + (size_t)lr * PP + pt + lc + u * 4);
            asT[lc + u * 4 + 0][lr] = av.x; asT[lc + u * 4 + 1][lr] = av.y;
            asT[lc + u * 4 + 2][lr] = av.z; asT[lc + u * 4 + 3][lr] = av.w;
            float4 vv = *reinterpret_cast<const float4*>(input + (size_t)(b * PP + pt + lr) * DD + h * HD_ + lc + u * 4);
            *reinterpret_cast<float4*>(&vs[lr][lc + u * 4]) = vv;
        }
        __syncthreads();
        #pragma unroll 16
        for (int k = 0; k < 64; ++k) {
            float4 ar = *reinterpret_cast<const float4*>(&asT[k][c0]);
            float4 vr = *reinterpret_cast<const float4*>(&vs[k][d0]);
            float arr[4] = {ar.x, ar.y, ar.z, ar.w};
            float vrr[4] = {vr.x, vr.y, vr.z, vr.w};
            #pragma unroll
            for (int i = 0; i < 4; ++i)
                #pragma unroll
                for (int j = 0; j < 4; ++j) acc[i][j] = fmaf(arr[i], vrr[j], acc[i][j]);
        }
        __syncthreads();
    }
    #pragma unroll
    for (int i = 0; i < 4; ++i) {
        float4 o = make_float4(acc[i][0], acc[i][1], acc[i][2], acc[i][3]);
        *reinterpret_cast<float4*>(vcore + (size_t)(bh * CC + c0 + i) * HD_ + d0) = o;
    }
}

// ---------------- v_patch + ffn_in concat (writes fp16) ----------------
__device__ __forceinline__ void cvt_store4(__half* ph, float4 v) {
    __half hb[4] = {__float2half_rn(v.x), __float2half_rn(v.y),
                    __float2half_rn(v.z), __float2half_rn(v.w)};
    *reinterpret_cast<uint2*>(ph) = *reinterpret_cast<const uint2*>(hb);
}

__global__ void __launch_bounds__(256) vpatch_ffn_kernel(
    const float* __restrict__ input, const float* __restrict__ vcore,
    const float* __restrict__ p2c, __half* __restrict__ fh)
{
    __shared__ float vc[64][65];
    __shared__ float ap[64][65];
    const int b = blockIdx.z, h = blockIdx.y, p0 = blockIdx.x * 64;
    const int bh = b * HH + h;
    const int tid = threadIdx.x;
    const int lr = tid >> 2;
    const int lc = (tid & 3) * 16;
    #pragma unroll
    for (int u = 0; u < 4; ++u) {
        float4 cv = *reinterpret_cast<const float4*>(vcore + (size_t)(bh * CC + lr) * HD_ + lc + u * 4);
        vc[lr][lc + u * 4 + 0] = cv.x; vc[lr][lc + u * 4 + 1] = cv.y;
        vc[lr][lc + u * 4 + 2] = cv.z; vc[lr][lc + u * 4 + 3] = cv.w;
        float4 av = *reinterpret_cast<const float4*>(p2c + ((size_t)(bh * CC + lr)) * PP + p0 + lc + u * 4);
        ap[lr][lc + u * 4 + 0] = av.x; ap[lr][lc + u * 4 + 1] = av.y;
        ap[lr][lc + u * 4 + 2] = av.z; ap[lr][lc + u * 4 + 3] = av.w;
    }
    __syncthreads();
    const int pq = (tid >> 4) * 4;
    const int d0 = (tid & 15) * 4;
    float acc[4][4];
    #pragma unroll
    for (int i = 0; i < 4; ++i)
        #pragma unroll
        for (int j = 0; j < 4; ++j) acc[i][j] = 0.0f;
    #pragma unroll 8
    for (int k = 0; k < 64; ++k) {
        float apr[4], vcr[4];
        #pragma unroll
        for (int i = 0; i < 4; ++i) apr[i] = ap[k][pq + i];
        #pragma unroll
        for (int j = 0; j < 4; ++j) vcr[j] = vc[k][d0 + j];
        #pragma unroll
        for (int i = 0; i < 4; ++i)
            #pragma unroll
            for (int j = 0; j < 4; ++j) acc[i][j] = fmaf(apr[i], vcr[j], acc[i][j]);
    }
    #pragma unroll
    for (int i = 0; i < 4; ++i) {
        const int gp = b * PP + p0 + pq + i;
        float4 inp = *reinterpret_cast<const float4*>(input + (size_t)gp * DD + h * HD_ + d0);
        float4 vp = make_float4(acc[i][0], acc[i][1], acc[i][2], acc[i][3]);
        float4 diff = make_float4(inp.x - vp.x, inp.y - vp.y, inp.z - vp.z, inp.w - vp.w);
        const size_t fo = (size_t)gp * FFNIN + h * HD_ + d0;
        cvt_store4(fh + fo, diff);
        cvt_store4(fh + fo + DD, vp);
    }
}

// ---------------- LayerNorm ----------------
__global__ void __launch_bounds__(128) ln_kernel(
    const float* __restrict__ x, const float* __restrict__ gamma,
    const float* __restrict__ beta, float* __restrict__ out)
{
    const float* row = x + (size_t)blockIdx.x * DD;
    const int t = threadIdx.x;
    float4 v = *reinterpret_cast<const float4*>(row + t * 4);
    float s = v.x + v.y + v.z + v.w;
    float sq = v.x * v.x + v.y * v.y + v.z * v.z + v.w * v.w;
    blockReduceSum2(s, sq);
    const float mu = s * (1.0f / DD);
    const float var = sq * (1.0f / DD) - mu * mu;
    const float rstd = rsqrtf(var + 1e-5f);
    float4 g = *reinterpret_cast<const float4*>(gamma + t * 4);
    float4 bt = *reinterpret_cast<const float4*>(beta + t * 4);
    float4 o;
    o.x = (v.x - mu) * rstd * g.x + bt.x;
    o.y = (v.y - mu) * rstd * g.y + bt.y;
    o.z = (v.z - mu) * rstd * g.z + bt.z;
    o.w = (v.w - mu) * rstd * g.w + bt.w;
    *reinterpret_cast<float4*>(out + (size_t)blockIdx.x * DD + t * 4) = o;
}

// ---------------- launch ----------------
extern "C" void kernel_launch(void* const* d_in, const int* in_sizes, int n_in,
                              void* d_out, int out_size)
{
    (void)in_sizes; (void)n_in; (void)out_size;
    const float* input = (const float*)d_in[0];
    const float* cores = (const float*)d_in[1];
    const float* Wv    = (const float*)d_in[2];
    const float* bv    = (const float*)d_in[3];
    const float* W1    = (const float*)d_in[4];
    const float* b1    = (const float*)d_in[5];
    const float* W2    = (const float*)d_in[6];
    const float* b2    = (const float*)d_in[7];
    const float* gamma = (const float*)d_in[8];
    const float* beta  = (const float*)d_in[9];
    float* out = (float*)d_out;

    float *q, *aff, *p2c, *vcore, *outp;
    __half *in_h, *ffn_h, *hid_h, *wvT, *w1T, *w2T;
    cudaGetSymbolAddress((void**)&q, g_q);
    cudaGetSymbolAddress((void**)&aff, g_aff);
    cudaGetSymbolAddress((void**)&p2c, g_p2c);
    cudaGetSymbolAddress((void**)&vcore, g_vcore);
    cudaGetSymbolAddress((void**)&outp, g_outp);
    cudaGetSymbolAddress((void**)&in_h, g_in_h);
    cudaGetSymbolAddress((void**)&ffn_h, g_ffn_h);
    cudaGetSymbolAddress((void**)&hid_h, g_hid_h);
    cudaGetSymbolAddress((void**)&wvT, g_wvT);
    cudaGetSymbolAddress((void**)&w1T, g_w1T);
    cudaGetSymbolAddress((void**)&w2T, g_w2T);

    cudaFuncSetAttribute(gemm_mma<0>, cudaFuncAttributeMaxDynamicSharedMemorySize, GEMM_SMEM);
    cudaFuncSetAttribute(gemm_mma<1>, cudaFuncAttributeMaxDynamicSharedMemorySize, GEMM_SMEM);
    cudaFuncSetAttribute(gemm_mma<2>, cudaFuncAttributeMaxDynamicSharedMemorySize, GEMM_SMEM);

    // prep: converts + weight transposes
    cvt_kernel<<<(MM * DD / 4 + 255) / 256, 256>>>(input, in_h, MM * DD / 4);
    transpose_h<<<dim3(DD / 32, DD / 32), 256>>>(Wv, wvT, DD, DD);
    transpose_h<<<dim3(FFNHID / 32, FFNIN / 32), 256>>>(W1, w1T, FFNIN, FFNHID);
    transpose_h<<<dim3(DD / 32, FFNHID / 32), 256>>>(W2, w2T, FFNHID, DD);

    // 1. q = input @ Wv + bv
    gemm_mma<0><<<dim3(DD / 128, MM / 128), 256, GEMM_SMEM>>>(
        in_h, wvT, bv, nullptr, q, nullptr, DD, DD);
    // 2-5. affinity + dual softmax + aggregate + redistribute
    aff_kernel<<<dim3(PP / 64, HH, BB), 256>>>(q, cores, aff);
    p2c_softmax<<<BB * HH, 256>>>(aff, p2c);
    c2p_softmax<<<BB * HH * CC, 256>>>(aff);
    vcore_kernel<<<dim3(HH, BB), 256>>>(input, aff, vcore);
    vpatch_ffn_kernel<<<dim3(PP / 64, HH, BB), 256>>>(input, vcore, p2c, ffn_h);
    // 6. hid = gelu(ffn @ W1 + b1)   (fp16 out)
    gemm_mma<1><<<dim3(FFNHID / 128, MM / 128), 256, GEMM_SMEM>>>(
        ffn_h, w1T, b1, nullptr, nullptr, hid_h, FFNHID, FFNIN);
    // 7. outp = input + hid @ W2 + b2
    gemm_mma<2><<<dim3(DD / 128, MM / 128), 256, GEMM_SMEM>>>(
        hid_h, w2T, b2, input, outp, nullptr, DD, FFNHID);
    // 8. LayerNorm
    ln_kernel<<<MM, 128>>>(outp, gamma, beta, out);
}